// round 12
// baseline (speedup 1.0000x reference)
#include <cuda_runtime.h>
#include <cooperative_groups.h>
#include <math.h>

namespace cg = cooperative_groups;

#define NB 4
#define SL 512
#define VOCAB 32000
#define DD 128
#define MM 8
#define NM 16
#define KK 153
#define LAMBDA 0.0025f
#define SCALE_D 0.08838834764831845f   /* 1/sqrt(128) */
#define SCALE_DH 0.17677669529663687f  /* 1/sqrt(32)  */

// ---------------- scratch ----------------
__device__ float g_x[NB*SL*DD];
__device__ float g_gates[NB*SL*MM];
__device__ float g_conn[SL*MM*MM];
__device__ float g_out[NB*SL*DD];
__device__ float g_q[NB*4*SL*32];
__device__ float g_k[NB*4*SL*32];
__device__ float g_v[NB*4*SL*32];
__device__ float g_ctx[NB*SL*DD];
__device__ float g_d1[NB*SL*DD];

// ---------------- helpers ----------------
__device__ __forceinline__ float wsum(float v) {
#pragma unroll
    for (int o = 16; o; o >>= 1) v += __shfl_xor_sync(0xffffffffu, v, o);
    return v;
}
__device__ __forceinline__ float wmaxf(float v) {
#pragma unroll
    for (int o = 16; o; o >>= 1) v = fmaxf(v, __shfl_xor_sync(0xffffffffu, v, o));
    return v;
}
__device__ __forceinline__ int wsumi(int v) {
#pragma unroll
    for (int o = 16; o; o >>= 1) v += __shfl_xor_sync(0xffffffffu, v, o);
    return v;
}
__device__ __forceinline__ unsigned long long ffma2(unsigned long long a,
                                                    unsigned long long b,
                                                    unsigned long long c) {
    unsigned long long d;
    asm("fma.rn.f32x2 %0, %1, %2, %3;" : "=l"(d) : "l"(a), "l"(b), "l"(c));
    return d;
}
__device__ __forceinline__ unsigned smaddr(const void* p) {
    unsigned a;
    asm("{ .reg .u64 t; cvta.to.shared.u64 t, %1; cvt.u32.u64 %0, t; }" : "=r"(a) : "l"(p));
    return a;
}

// ---------------- K0: embedding + pos ----------------
__global__ void embed_kernel(const int* __restrict__ seq,
                             const float* __restrict__ emb,
                             const float* __restrict__ pos) {
    int row = blockIdx.x;            // b*SL + s
    int d = threadIdx.x;
    int s = row & (SL - 1);
    int tok = seq[row];
    g_x[row * DD + d] = emb[tok * DD + d] + pos[s * DD + d];
}

// ---------------- K1: router gates ----------------
__global__ void gates_kernel(const float* __restrict__ Wr1, const float* __restrict__ br1,
                             const float* __restrict__ Wr2, const float* __restrict__ br2) {
    __shared__ float xs[8][DD];
    int warp = threadIdx.x >> 5, lane = threadIdx.x & 31;
    int row = blockIdx.x * 8 + warp;
    const float* xr = g_x + row * DD;
#pragma unroll
    for (int c = 0; c < 4; ++c) xs[warp][lane + 32 * c] = xr[lane + 32 * c];
    __syncwarp();

    float acc[4] = {0.f, 0.f, 0.f, 0.f};
    for (int k = 0; k < DD; ++k) {
        float a = xs[warp][k];
#pragma unroll
        for (int c = 0; c < 4; ++c) acc[c] = fmaf(a, Wr1[k * DD + lane + 32 * c], acc[c]);
    }
    float t1[4];
#pragma unroll
    for (int c = 0; c < 4; ++c) t1[c] = fmaxf(acc[c] + br1[lane + 32 * c], 0.f);

    float y[MM];
#pragma unroll
    for (int m = 0; m < MM; ++m) {
        float p = 0.f;
#pragma unroll
        for (int c = 0; c < 4; ++c) p = fmaf(t1[c], Wr2[(lane + 32 * c) * MM + m], p);
        p = wsum(p);
        y[m] = p + br2[m];
    }
    float mx = y[0];
#pragma unroll
    for (int m = 1; m < MM; ++m) mx = fmaxf(mx, y[m]);
    float ssum = 0.f;
#pragma unroll
    for (int m = 0; m < MM; ++m) { y[m] = expf(y[m] - mx); ssum += y[m]; }
    if (lane == 0) {
        float inv = 1.f / ssum;
#pragma unroll
        for (int m = 0; m < MM; ++m) g_gates[row * MM + m] = y[m] * inv;
    }
}

// ---------------- K2: Hebbian conn prefix ----------------
__global__ void conn_kernel(const float* __restrict__ conn0) {
    extern __shared__ float gs[];   // NB*SL*MM floats
    int tid = threadIdx.x;          // 64 threads
    for (int i = tid; i < NB * SL * MM; i += 64) gs[i] = g_gates[i];
    __syncthreads();
    int i = tid >> 3, j = tid & 7;
    float c = conn0[tid];
    for (int t = 0; t < SL; ++t) {
        g_conn[t * 64 + tid] = c;
        float v = 0.f;
#pragma unroll
        for (int b = 0; b < NB; ++b)
            v += gs[(b * SL + t) * MM + i] * gs[(b * SL + t) * MM + j];
        c += LAMBDA * v;
    }
}

// ---------------- K3: scan — rank-1 score fusion + all-warp reduces ----------------
// SMEM float offsets
#define XW3   0        // 16384 (own module eW3)
#define XMEM  16384    // 2048
#define XB1   18432
#define XE1G  18560
#define XE1B  18688
#define XB2   18816
#define XE2G  18944
#define XE2B  19072
#define XB3   19200
#define XLNG  19328
#define XLNB  19456
#define XCUR  19584
#define XCOMB 19712
#define XV1   19840
#define XV2   19968
#define XAGG  20096
#define XSOWN 20224
#define XST0  20352    // 1024 (states, parity 0)
#define XST1  21376    // 1024 (states, parity 1)
#define XSA   22400    // 1024
#define XSB   23424    // 1024
#define XPART 24448    // 2048
#define XATR0 26496    // 16 (read scores, parity 0)
#define XATR1 26512    // 16 (read scores, parity 1)
#define XATTW 26528    // 16 (write-attention scores)
#define XG    26544    // 8
#define XCR   26552    // 8
#define XCG   26560    // 8
#define XMB   26568    // 8 (3 mbarriers: +0,+2,+4)
#define XWM   26576    // 16384 (Wmsg)
#define XTOT  42960
#define SCAN_SMEM_BYTES (XTOT * 4)
#define EXCH_BYTES 4096u   /* 8 ranks x 128 floats */

// warp-replicated LN stats of a 128-vector at sm[off] -> mean, inv
__device__ __forceinline__ void ln_stats(const float* sm, int off, int lane,
                                         float& mean, float& inv) {
    float a0 = sm[off + lane], a1 = sm[off + 32 + lane];
    float a2 = sm[off + 64 + lane], a3 = sm[off + 96 + lane];
    float s1 = wsum(a0 + a1 + a2 + a3);
    float s2 = wsum(fmaf(a0, a0, fmaf(a1, a1, fmaf(a2, a2, a3 * a3))));
    mean = s1 * (1.f / 128.f);
    float var = s2 * (1.f / 128.f) - mean * mean;
    inv = rsqrtf(var + 1e-5f);
}

// all-warp slice reduce: warp w reduces partials for idx = 8w + (lane&7).
// returns the full 16-partial sum (valid in all lanes; lanes<8 are canonical).
__device__ __forceinline__ float redslice(const float* sm, int warp, int lane) {
    int idx = warp * 8 + (lane & 7);
    int q0 = (lane >> 3) * 4;
    float v = sm[XPART + q0 * 128 + idx] + sm[XPART + (q0 + 1) * 128 + idx]
            + sm[XPART + (q0 + 2) * 128 + idx] + sm[XPART + (q0 + 3) * 128 + idx];
    v += __shfl_xor_sync(0xffffffffu, v, 8);
    v += __shfl_xor_sync(0xffffffffu, v, 16);
    return v;
}

// push value v into slot (rank*128 + d) of buffer `dstoff` in ALL 8 cluster CTAs,
// signaling each peer's mbarrier via st.async transaction bytes.
__device__ __forceinline__ void push_async(float* sm, int dstoff, int mboff,
                                           int rank, int d, float v) {
    unsigned dst0 = smaddr(sm + dstoff + rank * 128 + d);
    unsigned mb0 = smaddr(sm + mboff);
    unsigned vi = __float_as_uint(v);
#pragma unroll
    for (int r = 0; r < MM; ++r) {
        unsigned dst, mb;
        asm("mapa.shared::cluster.u32 %0, %1, %2;" : "=r"(dst) : "r"(dst0), "r"(r));
        asm("mapa.shared::cluster.u32 %0, %1, %2;" : "=r"(mb) : "r"(mb0), "r"(r));
        asm volatile("st.async.shared::cluster.mbarrier::complete_tx::bytes.b32 [%0], %1, [%2];"
                     :: "r"(dst), "r"(vi), "r"(mb) : "memory");
    }
}

__device__ __forceinline__ void mbar_wait(float* sm, int mboff, unsigned parity) {
    unsigned mb = smaddr(sm + mboff);
    asm volatile(
        "{\n\t.reg .pred P;\n"
        "W%=:\n\t"
        "mbarrier.try_wait.parity.acquire.cluster.shared::cta.b64 P, [%0], %1, 0x989680;\n\t"
        "@P bra.uni D%=;\n\t"
        "bra.uni W%=;\n"
        "D%=:\n\t}"
        :: "r"(mb), "r"(parity) : "memory");
}

__global__ void __launch_bounds__(512, 1) __cluster_dims__(MM, 1, 1) scan_kernel(
    const float* __restrict__ mem0, const float* __restrict__ Wmsg,
    const float* __restrict__ ln_g, const float* __restrict__ ln_b,
    const float* __restrict__ eW1, const float* __restrict__ eb1,
    const float* __restrict__ e1g, const float* __restrict__ e1b,
    const float* __restrict__ eW2, const float* __restrict__ eb2,
    const float* __restrict__ e2g, const float* __restrict__ e2b,
    const float* __restrict__ eW3, const float* __restrict__ eb3) {
    extern __shared__ float sm[];
    cg::cluster_group cluster = cg::this_cluster();
    int tid = threadIdx.x;
    int rank = (int)cluster.block_rank();        // module index
    int b = blockIdx.x >> 3;                     // batch index
    int warp = tid >> 5, lane = tid & 31;        // warp == k-group (16)

    // register-resident W1, W2: thread (kq=warp, jq=lane) holds its 8 weight quads
    float4 w1r[8], w2r[8];
    {
        const float4* W1g = reinterpret_cast<const float4*>(eW1 + (size_t)rank * 16384);
        const float4* W2g = reinterpret_cast<const float4*>(eW2 + (size_t)rank * 16384);
        int base = (warp * 8) * 32 + lane;
#pragma unroll
        for (int k = 0; k < 8; ++k) {
            w1r[k] = W1g[base + k * 32];
            w2r[k] = W2g[base + k * 32];
        }
        const float* w3 = eW3 + (size_t)rank * 16384;
        for (int i = tid; i < 16384; i += 512) {
            sm[XW3 + i] = w3[i];
            sm[XWM + i] = Wmsg[i];
        }
        for (int i = tid; i < 2048; i += 512) sm[XMEM + i] = mem0[i];
        if (tid < 128) {
            sm[XB1 + tid]  = eb1[rank * 128 + tid];
            sm[XE1G + tid] = e1g[rank * 128 + tid];
            sm[XE1B + tid] = e1b[rank * 128 + tid];
            sm[XB2 + tid]  = eb2[rank * 128 + tid];
            sm[XE2G + tid] = e2g[rank * 128 + tid];
            sm[XE2B + tid] = e2b[rank * 128 + tid];
            sm[XB3 + tid]  = eb3[rank * 128 + tid];
            sm[XLNG + tid] = ln_g[tid];
            sm[XLNB + tid] = ln_b[tid];
        }
        // t=0 step inputs
        if (tid < 128) sm[XCUR + tid] = g_x[(b * SL) * DD + tid];
        else if (tid < 136) sm[XG + tid - 128] = g_gates[(b * SL) * MM + (tid - 128)];
        else if (tid < 144) sm[XCR + tid - 136] = g_conn[rank * 8 + (tid - 136)];
        if (tid == 0) {
#pragma unroll
            for (int q = 0; q < 3; ++q) {
                unsigned mb = smaddr(sm + XMB + 2 * q);
                asm volatile("mbarrier.init.shared.b64 [%0], %1;" :: "r"(mb), "r"(1u) : "memory");
            }
        }
    }
    cluster.sync();   // all SMEM + mbarriers ready cluster-wide

    // prologue: read-attention scores for t=0
    {
        float pp = 0.f;
#pragma unroll
        for (int c = 0; c < 4; ++c) {
            int k = lane + 32 * c;
            pp = fmaf(sm[XCUR + k], sm[XMEM + warp * DD + k], pp);
        }
        pp = wsum(pp);
        if (lane == 0) sm[XATR0 + warp] = pp * SCALE_D;
    }
    __syncthreads();

    float4* part4 = reinterpret_cast<float4*>(sm + XPART);
    const float4* Wm4 = reinterpret_cast<const float4*>(sm + XWM) + (warp * 8) * 32 + lane;
    const float4* W34 = reinterpret_cast<const float4*>(sm + XW3) + (warp * 8) * 32 + lane;

    for (int t = 0; t < SL; ++t) {
        int xst = (t & 1) ? XST1 : XST0;
        int xatr = (t & 1) ? XATR1 : XATR0;
        int nxatr = (t & 1) ? XATR0 : XATR1;
        unsigned par = (unsigned)(t & 1);
        if (tid == 0) {
#pragma unroll
            for (int q = 0; q < 3; ++q) {
                unsigned mb = smaddr(sm + XMB + 2 * q);
                asm volatile("mbarrier.arrive.expect_tx.shared.b64 _, [%0], %1;"
                             :: "r"(mb), "r"(EXCH_BYTES) : "memory");
            }
        } else if (tid >= 32 && tid < 40) sm[XCG + tid - 32] = sm[XCR + tid - 32] * sm[XG + tid - 32];
        // prefetch t+1 inputs into regs
        float pref = 0.f;
        if (t < SL - 1) {
            if (tid < 128) pref = g_x[(b * SL + t + 1) * DD + tid];
            else if (tid < 136) pref = g_gates[(b * SL + t + 1) * MM + (tid - 128)];
            else if (tid < 144) pref = g_conn[(t + 1) * 64 + rank * 8 + (tid - 136)];
        }

        // A: comb = cur + retrieved (softmax over precomputed scores), warps 0-3
        if (tid < 128) {
            float vv = (lane < NM) ? sm[xatr + lane] : -1e30f;
            float mx = wmaxf(vv);
            float e = (lane < NM) ? expf(vv - mx) : 0.f;
            float ss = wsum(e);
            float aval = e / ss;
            float r = 0.f;
#pragma unroll
            for (int n = 0; n < NM; ++n) {
                float an = __shfl_sync(0xffffffffu, aval, n);
                r = fmaf(an, sm[XMEM + n * DD + tid], r);
            }
            sm[XCOMB + tid] = sm[XCUR + tid] + r;
        }
        __syncthreads();                                              // B1

        // L1: inline LN(comb) -> matvec with w1r
        {
            float mean, inv;
            ln_stats(sm, XCOMB, lane, mean, inv);
            float4 acc = make_float4(0.f, 0.f, 0.f, 0.f);
#pragma unroll
            for (int k = 0; k < 8; ++k) {
                int idx = warp * 8 + k;
                float xv = (sm[XCOMB + idx] - mean) * inv * sm[XLNG + idx] + sm[XLNB + idx];
                float4 w = w1r[k];
                acc.x = fmaf(xv, w.x, acc.x); acc.y = fmaf(xv, w.y, acc.y);
                acc.z = fmaf(xv, w.z, acc.z); acc.w = fmaf(xv, w.w, acc.w);
            }
            part4[warp * 32 + lane] = acc;
        }
        __syncthreads();                                              // B2
        {
            float v = redslice(sm, warp, lane) + sm[XB1 + warp * 8 + (lane & 7)];
            if (lane < 8) sm[XV1 + warp * 8 + lane] = v;
        }
        __syncthreads();                                              // B3

        // L2: inline relu(LN(v1)) -> matvec with w2r
        {
            float mean, inv;
            ln_stats(sm, XV1, lane, mean, inv);
            float4 acc = make_float4(0.f, 0.f, 0.f, 0.f);
#pragma unroll
            for (int k = 0; k < 8; ++k) {
                int idx = warp * 8 + k;
                float xv = fmaxf((sm[XV1 + idx] - mean) * inv * sm[XE1G + idx] + sm[XE1B + idx], 0.f);
                float4 w = w2r[k];
                acc.x = fmaf(xv, w.x, acc.x); acc.y = fmaf(xv, w.y, acc.y);
                acc.z = fmaf(xv, w.z, acc.z); acc.w = fmaf(xv, w.w, acc.w);
            }
            part4[warp * 32 + lane] = acc;
        }
        __syncthreads();                                              // B4
        {
            float v = redslice(sm, warp, lane) + sm[XB2 + warp * 8 + (lane & 7)];
            if (lane < 8) sm[XV2 + warp * 8 + lane] = v;
        }
        __syncthreads();                                              // B5

        // L3: inline relu(LN(v2)) -> matvec with SMEM W3
        {
            float mean, inv;
            ln_stats(sm, XV2, lane, mean, inv);
            float4 acc = make_float4(0.f, 0.f, 0.f, 0.f);
#pragma unroll
            for (int k = 0; k < 8; ++k) {
                int idx = warp * 8 + k;
                float xv = fmaxf((sm[XV2 + idx] - mean) * inv * sm[XE2G + idx] + sm[XE2B + idx], 0.f);
                float4 w = W34[k * 32];
                acc.x = fmaf(xv, w.x, acc.x); acc.y = fmaf(xv, w.y, acc.y);
                acc.z = fmaf(xv, w.z, acc.z); acc.w = fmaf(xv, w.w, acc.w);
            }
            part4[warp * 32 + lane] = acc;
        }
        __syncthreads();                                              // B6

        // P1: slice reduce + push states
        {
            int idx = warp * 8 + (lane & 7);
            float v = redslice(sm, warp, lane) + sm[XB3 + idx];
            if (lane < 8) {
                sm[XSOWN + idx] = v;
                push_async(sm, xst, XMB + 0, rank, idx, v);
            }
        }
        mbar_wait(sm, XMB + 0, par);                                  // E1

        // MP1: warp-local msg (lanes<8) + shfl, matvec with Wmsg (SMEM)
        {
            float msgv = 0.f;
            if (lane < 8) {
                int k = warp * 8 + lane;
#pragma unroll
                for (int jm = 0; jm < MM; ++jm)
                    msgv = fmaf(sm[XCG + jm], sm[xst + jm * 128 + k], msgv);
            }
            float4 acc = make_float4(0.f, 0.f, 0.f, 0.f);
#pragma unroll
            for (int k = 0; k < 8; ++k) {
                float xv = __shfl_sync(0xffffffffu, msgv, k);
                float4 w = Wm4[k * 32];
                acc.x = fmaf(xv, w.x, acc.x); acc.y = fmaf(xv, w.y, acc.y);
                acc.z = fmaf(xv, w.z, acc.z); acc.w = fmaf(xv, w.w, acc.w);
            }
            part4[warp * 32 + lane] = acc;
        }
        __syncthreads();                                              // B7

        // P2: slice reduce + s update + push XSA
        {
            int idx = warp * 8 + (lane & 7);
            float y = redslice(sm, warp, lane);
            if (lane < 8) {
                float ns = sm[XSOWN + idx] + fmaxf(y, 0.f);
                sm[XSOWN + idx] = ns;
                push_async(sm, XSA, XMB + 2, rank, idx, ns);
            }
        }
        mbar_wait(sm, XMB + 2, par);                                  // E2

        // MP2 + store cur(t+1) into XCUR (last reader of cur(t) was phase A)
        {
            if (tid < 128 && t < SL - 1) sm[XCUR + tid] = pref;
            float msgv = 0.f;
            if (lane < 8) {
                int k = warp * 8 + lane;
#pragma unroll
                for (int jm = 0; jm < MM; ++jm)
                    msgv = fmaf(sm[XCG + jm], sm[XSA + jm * 128 + k], msgv);
            }
            float4 acc = make_float4(0.f, 0.f, 0.f, 0.f);
#pragma unroll
            for (int k = 0; k < 8; ++k) {
                float xv = __shfl_sync(0xffffffffu, msgv, k);
                float4 w = Wm4[k * 32];
                acc.x = fmaf(xv, w.x, acc.x); acc.y = fmaf(xv, w.y, acc.y);
                acc.z = fmaf(xv, w.z, acc.z); acc.w = fmaf(xv, w.w, acc.w);
            }
            part4[warp * 32 + lane] = acc;
        }
        __syncthreads();                                              // B8

        // P3: slice reduce + push final s to XSB
        {
            int idx = warp * 8 + (lane & 7);
            float y = redslice(sm, warp, lane);
            if (lane < 8) {
                float v = sm[XSOWN + idx] + fmaxf(y, 0.f);
                push_async(sm, XSB, XMB + 4, rank, idx, v);
            }
        }
        mbar_wait(sm, XMB + 4, par);                                  // E3

        // AGG + write-attention scores (pre-softmax) -> XATTW
        {
            float aggc[4];
#pragma unroll
            for (int c = 0; c < 4; ++c) {
                int k = lane + 32 * c;
                float a = 0.f, ms = 0.f;
#pragma unroll
                for (int m = 0; m < MM; ++m) {
                    a = fmaf(sm[XG + m], sm[xst + m * 128 + k], a);
                    ms += sm[XSB + m * 128 + k];
                }
                aggc[c] = a + 0.125f * ms;
            }
            float p = 0.f;
#pragma unroll
            for (int c = 0; c < 4; ++c)
                p = fmaf(aggc[c], sm[XMEM + warp * DD + lane + 32 * c], p);
            p = wsum(p);
            if (lane == 0) sm[XATTW + warp] = p * SCALE_D;
            if (warp < 4) {
                float av = aggc[0];
                av = (warp == 1) ? aggc[1] : av;
                av = (warp == 2) ? aggc[2] : av;
                av = (warp == 3) ? aggc[3] : av;
                int k = lane + 32 * warp;
                sm[XAGG + k] = av;
                if (rank == 0) g_out[(b * SL + t) * DD + k] = av;
            }
        }
        __syncthreads();                                              // B9

        // TAIL: mem update + rank-1 fused read-scores for t+1 (skip at last step)
        if (t < SL - 1) {
            float vv = (lane < NM) ? sm[XATTW + lane] : -1e30f;
            float mx = wmaxf(vv);
            float e = (lane < NM) ? expf(vv - mx) : 0.f;
            float ss = wsum(e);
            float aval = e / ss;
            float wn = __shfl_sync(0xffffffffu, aval, warp);
            float memv[4], aggv[4], curv[4];
            float p = 0.f, qd = 0.f;
#pragma unroll
            for (int c = 0; c < 4; ++c) {
                int k = lane + 32 * c;
                memv[c] = sm[XMEM + warp * DD + k];
                aggv[c] = sm[XAGG + k];
                curv[c] = sm[XCUR + k];          // cur(t+1), stored in MP2 phase
                p = fmaf(curv[c], memv[c], p);
                qd = fmaf(curv[c], aggv[c], qd);
            }
            p = wsum(p); qd = wsum(qd);
#pragma unroll
            for (int c = 0; c < 4; ++c) {
                int k = lane + 32 * c;
                sm[XMEM + warp * DD + k] = fmaf(wn, aggv[c], memv[c]);
            }
            if (lane == 0) sm[nxatr + warp] = (p + wn * qd) * SCALE_D;
            if (tid >= 128 && tid < 136) sm[XG + tid - 128] = pref;
            else if (tid >= 136 && tid < 144) sm[XCR + tid - 136] = pref;
        }
        __syncthreads();                                              // B10
    }
}

// ---------------- K4: QKV projections ----------------
__global__ void qkv_kernel(const float* __restrict__ Wq, const float* __restrict__ Wk,
                           const float* __restrict__ Wv) {
    __shared__ float xs[32 * 128];
    int tid = threadIdx.x;
    int rowbase = blockIdx.x * 32;
    for (int idx = tid; idx < 4096; idx += 256) xs[idx] = g_out[rowbase * 128 + idx];
    __syncthreads();
    int rh = tid >> 7, jj = tid & 127;
    const float* Ws[3] = {Wq, Wk, Wv};
    float* Os[3] = {g_q, g_k, g_v};
#pragma unroll 1
    for (int w = 0; w < 3; ++w) {
        float acc[16];
#pragma unroll
        for (int r = 0; r < 16; ++r) acc[r] = 0.f;
        const float* W = Ws[w];
        for (int k = 0; k < 128; ++k) {
            float wv = W[k * 128 + jj];
#pragma unroll
            for (int r = 0; r < 16; ++r) acc[r] = fmaf(xs[(rh * 16 + r) * 128 + k], wv, acc[r]);
        }
        int h = jj >> 5, dh = jj & 31;
#pragma unroll
        for (int r = 0; r < 16; ++r) {
            int row = rowbase + rh * 16 + r;
            int bb = row >> 9, s = row & 511;
            Os[w][((bb * 4 + h) * SL + s) * 32 + dh] = acc[r];
        }
    }
}

// ---------------- K5: sparse attention ----------------
__global__ void __launch_bounds__(256) attn_kernel() {
    extern __shared__ float ash[];
    float* kt = ash;              // 16384
    float* vt = ash + 16384;      // 16384
    float* cp = ash + 32768;      // 8192
    int tid = threadIdx.x, warp = tid >> 5, lane = tid & 31;
    int bh = blockIdx.x;
    const float* kb = g_k + bh * SL * 32;
    const float* vb = g_v + bh * SL * 32;
    for (int idx = tid; idx < SL * 32; idx += 256) {
        int n = idx >> 5, dh = idx & 31, sw = (dh + n) & 31;
        kt[n * 32 + sw] = kb[idx];
        vt[n * 32 + sw] = vb[idx];
    }
    __syncthreads();

    int qrow = blockIdx.y * 8 + warp;
    float qv = g_q[bh * SL * 32 + qrow * 32 + lane];
    float sc[16];
#pragma unroll
    for (int c = 0; c < 16; ++c) sc[c] = 0.f;
    for (int dh = 0; dh < 32; ++dh) {
        float qd = __shfl_sync(0xffffffffu, qv, dh);
#pragma unroll
        for (int c = 0; c < 16; ++c) {
            int n = c * 32 + lane;
            sc[c] = fmaf(qd, kt[n * 32 + ((dh + n) & 31)], sc[c]);
        }
    }
#pragma unroll
    for (int c = 0; c < 16; ++c) sc[c] *= SCALE_DH;

    unsigned eu[16];
#pragma unroll
    for (int c = 0; c < 16; ++c) {
        unsigned u = __float_as_uint(sc[c]);
        eu[c] = (u & 0x80000000u) ? ~u : (u | 0x80000000u);
    }
    unsigned thr = 0;
    for (int bit = 31; bit >= 0; --bit) {
        unsigned cand = thr | (1u << bit);
        int cnt = 0;
#pragma unroll
        for (int c = 0; c < 16; ++c) cnt += (eu[c] >= cand) ? 1 : 0;
        cnt = wsumi(cnt);
        if (cnt >= KK) thr = cand;
    }

    float mloc = -1e30f;
#pragma unroll
    for (int c = 0; c < 16; ++c) mloc = fmaxf(mloc, sc[c]);
    float mx = wmaxf(mloc);
    float ssum = 0.f;
#pragma unroll
    for (int c = 0; c < 16; ++c) ssum += (eu[c] >= thr) ? expf(sc[c] - mx) : 0.f;
    ssum = wsum(ssum);
    float inv = 1.f / ssum;

    float cx[32];
#pragma unroll
    for (int dh = 0; dh < 32; ++dh) cx[dh] = 0.f;
#pragma unroll 1
    for (int c = 0; c < 16; ++c) {
        float a = (eu[c] >= thr) ? expf(sc[c] - mx) * inv : 0.f;
        int n = c * 32 + lane;
#pragma unroll
        for (int dh = 0; dh < 32; ++dh)
            cx[dh] = fmaf(a, vt[n * 32 + ((dh + n) & 31)], cx[dh]);
    }

    float* cw = cp + warp * 1024;
#pragma unroll
    for (int dh = 0; dh < 32; ++dh) cw[lane * 32 + ((dh + lane) & 31)] = cx[dh];
    __syncwarp();
    float tot = 0.f;
#pragma unroll
    for (int src = 0; src < 32; ++src) tot += cw[src * 32 + ((lane + src) & 31)];
    int bb = bh >> 2, h = bh & 3;
    g_ctx[(bb * SL + qrow) * DD + h * 32 + lane] = tot;
}

// ---------------- K6: small 128x128 GEMMs ----------------
__global__ void gemm128_kernel(const float* __restrict__ W, const float* __restrict__ bias,
                               int mode) {
    __shared__ float xs[32 * 128];
    const float* in = mode ? g_out : g_ctx;
    float* out = mode ? g_d1 : g_out;
    int tid = threadIdx.x;
    int rowbase = blockIdx.x * 32;
    for (int idx = tid; idx < 4096; idx += 256) xs[idx] = in[rowbase * 128 + idx];
    __syncthreads();
    int rh = tid >> 7, jj = tid & 127;
    float acc[16];
#pragma unroll
    for (int r = 0; r < 16; ++r) acc[r] = 0.f;
    for (int k = 0; k < 128; ++k) {
        float wv = W[k * 128 + jj];
#pragma unroll
        for (int r = 0; r < 16; ++r) acc[r] = fmaf(xs[(rh * 16 + r) * 128 + k], wv, acc[r]);
    }
    float bb = mode ? bias[jj] : 0.f;
#pragma unroll
    for (int r = 0; r < 16; ++r) {
        float v = acc[r] + bb;
        if (mode) v = fmaxf(v, 0.f);
        out[(rowbase + rh * 16 + r) * 128 + jj] = v;
    }
}

// ---------------- K7: decoder [2048,128]@[128,32000] with f32x2 FMA ----------------
__global__ void __launch_bounds__(256) decoder_kernel(const float* __restrict__ Wd2,
                                                      const float* __restrict__ bd2,
                                                      float* __restrict__ out) {
    extern __shared__ float At[];   // 128*132 transposed A tile
    int tid = threadIdx.x;
    int rowbase = blockIdx.x * 128;
    for (int idx = tid; idx < 16384; idx += 256) {
        int r = idx >> 7, k = idx & 127;
        At[k * 132 + r] = g_d1[(rowbase + r) * 128 + k];
    }
    __syncthreads();
    int j = blockIdx.y * 64 + (tid & 63);
    int rq = tid >> 6;
    unsigned long long acc2[16];
#pragma unroll
    for (int i = 0; i < 16; ++i) acc2[i] = 0ull;
    const float* Bp = Wd2 + j;
    for (int k = 0; k < 128; ++k) {
        float w = Bp[(size_t)k * VOCAB];
        unsigned long long wp;
        asm("mov.b64 %0, {%1, %1};" : "=l"(wp) : "f"(w));
        const ulonglong2* a2 = reinterpret_cast<const ulonglong2*>(At + k * 132) + rq * 8;
#pragma unroll
        for (int rr = 0; rr < 8; ++rr) {
            ulonglong2 p = a2[rr];
            acc2[rr * 2]     = ffma2(p.x, wp, acc2[rr * 2]);
            acc2[rr * 2 + 1] = ffma2(p.y, wp, acc2[rr * 2 + 1]);
        }
    }
    float bb = bd2[j];
#pragma unroll
    for (int i = 0; i < 16; ++i) {
        float lo, hi;
        asm("mov.b64 {%0, %1}, %2;" : "=f"(lo), "=f"(hi) : "l"(acc2[i]));
        int row = rowbase + rq * 32 + i * 2;
        out[(size_t)row * VOCAB + j] = lo + bb;
        out[(size_t)(row + 1) * VOCAB + j] = hi + bb;
    }
}

// ---------------- launch ----------------
extern "C" void kernel_launch(void* const* d_in, const int* in_sizes, int n_in,
                              void* d_out, int out_size) {
    int off = (n_in > 30) ? 1 : 0;  // skip task_id if present
    const int*   seq  = (const int*)d_in[0];
    const float* emb  = (const float*)d_in[1 + off];
    const float* pos  = (const float*)d_in[2 + off];
    const float* Wr1  = (const float*)d_in[3 + off];
    const float* br1  = (const float*)d_in[4 + off];
    const float* Wr2  = (const float*)d_in[5 + off];
    const float* br2  = (const float*)d_in[6 + off];
    const float* ln_g = (const float*)d_in[7 + off];
    const float* ln_b = (const float*)d_in[8 + off];
    const float* eW1  = (const float*)d_in[9 + off];
    const float* eb1  = (const float*)d_in[10 + off];
    const float* e1g  = (const float*)d_in[11 + off];
    const float* e1b  = (const float*)d_in[12 + off];
    const float* eW2  = (const float*)d_in[13 + off];
    const float* eb2  = (const float*)d_in[14 + off];
    const float* e2g  = (const float*)d_in[15 + off];
    const float* e2b  = (const float*)d_in[16 + off];
    const float* eW3  = (const float*)d_in[17 + off];
    const float* eb3  = (const float*)d_in[18 + off];
    const float* mem0 = (const float*)d_in[19 + off];
    const float* Wmsg = (const float*)d_in[20 + off];
    const float* conn0= (const float*)d_in[21 + off];
    const float* Wq   = (const float*)d_in[22 + off];
    const float* Wk   = (const float*)d_in[23 + off];
    const float* Wv   = (const float*)d_in[24 + off];
    const float* Wo   = (const float*)d_in[25 + off];
    const float* Wd1  = (const float*)d_in[26 + off];
    const float* bd1  = (const float*)d_in[27 + off];
    const float* Wd2  = (const float*)d_in[28 + off];
    const float* bd2  = (const float*)d_in[29 + off];

    cudaFuncSetAttribute(conn_kernel, cudaFuncAttributeMaxDynamicSharedMemorySize, NB * SL * MM * 4);
    cudaFuncSetAttribute(scan_kernel, cudaFuncAttributeMaxDynamicSharedMemorySize, SCAN_SMEM_BYTES);
    cudaFuncSetAttribute(attn_kernel, cudaFuncAttributeMaxDynamicSharedMemorySize, 40960 * 4);
    cudaFuncSetAttribute(decoder_kernel, cudaFuncAttributeMaxDynamicSharedMemorySize, 128 * 132 * 4);

    embed_kernel<<<NB * SL, DD>>>(seq, emb, pos);
    gates_kernel<<<NB * SL / 8, 256>>>(Wr1, br1, Wr2, br2);
    conn_kernel<<<1, 64, NB * SL * MM * 4>>>(conn0);
    scan_kernel<<<NB * MM, 512, SCAN_SMEM_BYTES>>>(mem0, Wmsg, ln_g, ln_b,
                                                   eW1, eb1, e1g, e1b,
                                                   eW2, eb2, e2g, e2b, eW3, eb3);
    qkv_kernel<<<NB * SL / 32, 256>>>(Wq, Wk, Wv);
    attn_kernel<<<dim3(NB * 4, SL / 8), 256, 40960 * 4>>>();
    gemm128_kernel<<<NB * SL / 32, 256>>>(Wo, bd1, 0);   // ctx @ Wo -> g_out
    gemm128_kernel<<<NB * SL / 32, 256>>>(Wd1, bd1, 1);  // relu(g_out @ Wd1 + bd1) -> g_d1
    decoder_kernel<<<dim3(NB * SL / 128, VOCAB / 64), 256, 128 * 132 * 4>>>(Wd2, bd2, (float*)d_out);
}

// round 13
// speedup vs baseline: 1.2361x; 1.2361x over previous
#include <cuda_runtime.h>
#include <cooperative_groups.h>
#include <math.h>

namespace cg = cooperative_groups;

#define NB 4
#define SL 512
#define VOCAB 32000
#define DD 128
#define MM 8
#define NM 16
#define KK 153
#define LAMBDA 0.0025f
#define SCALE_D 0.08838834764831845f   /* 1/sqrt(128) */
#define SCALE_DH 0.17677669529663687f  /* 1/sqrt(32)  */

// ---------------- scratch ----------------
__device__ float g_x[NB*SL*DD];
__device__ float g_gates[NB*SL*MM];
__device__ float g_conn[SL*MM*MM];
__device__ float g_out[NB*SL*DD];
__device__ float g_q[NB*4*SL*32];
__device__ float g_k[NB*4*SL*32];
__device__ float g_v[NB*4*SL*32];
__device__ float g_ctx[NB*SL*DD];
__device__ float g_d1[NB*SL*DD];

// ---------------- helpers ----------------
__device__ __forceinline__ float wsum(float v) {
#pragma unroll
    for (int o = 16; o; o >>= 1) v += __shfl_xor_sync(0xffffffffu, v, o);
    return v;
}
__device__ __forceinline__ float wmaxf(float v) {
#pragma unroll
    for (int o = 16; o; o >>= 1) v = fmaxf(v, __shfl_xor_sync(0xffffffffu, v, o));
    return v;
}
__device__ __forceinline__ int wsumi(int v) {
#pragma unroll
    for (int o = 16; o; o >>= 1) v += __shfl_xor_sync(0xffffffffu, v, o);
    return v;
}
__device__ __forceinline__ unsigned long long ffma2(unsigned long long a,
                                                    unsigned long long b,
                                                    unsigned long long c) {
    unsigned long long d;
    asm("fma.rn.f32x2 %0, %1, %2, %3;" : "=l"(d) : "l"(a), "l"(b), "l"(c));
    return d;
}
__device__ __forceinline__ unsigned smaddr(const void* p) {
    unsigned a;
    asm("{ .reg .u64 t; cvta.to.shared.u64 t, %1; cvt.u32.u64 %0, t; }" : "=r"(a) : "l"(p));
    return a;
}

// ---------------- K0: embedding + pos ----------------
__global__ void embed_kernel(const int* __restrict__ seq,
                             const float* __restrict__ emb,
                             const float* __restrict__ pos) {
    int row = blockIdx.x;            // b*SL + s
    int d = threadIdx.x;
    int s = row & (SL - 1);
    int tok = seq[row];
    g_x[row * DD + d] = emb[tok * DD + d] + pos[s * DD + d];
}

// ---------------- K1: router gates ----------------
__global__ void gates_kernel(const float* __restrict__ Wr1, const float* __restrict__ br1,
                             const float* __restrict__ Wr2, const float* __restrict__ br2) {
    __shared__ float xs[8][DD];
    int warp = threadIdx.x >> 5, lane = threadIdx.x & 31;
    int row = blockIdx.x * 8 + warp;
    const float* xr = g_x + row * DD;
#pragma unroll
    for (int c = 0; c < 4; ++c) xs[warp][lane + 32 * c] = xr[lane + 32 * c];
    __syncwarp();

    float acc[4] = {0.f, 0.f, 0.f, 0.f};
    for (int k = 0; k < DD; ++k) {
        float a = xs[warp][k];
#pragma unroll
        for (int c = 0; c < 4; ++c) acc[c] = fmaf(a, Wr1[k * DD + lane + 32 * c], acc[c]);
    }
    float t1[4];
#pragma unroll
    for (int c = 0; c < 4; ++c) t1[c] = fmaxf(acc[c] + br1[lane + 32 * c], 0.f);

    float y[MM];
#pragma unroll
    for (int m = 0; m < MM; ++m) {
        float p = 0.f;
#pragma unroll
        for (int c = 0; c < 4; ++c) p = fmaf(t1[c], Wr2[(lane + 32 * c) * MM + m], p);
        p = wsum(p);
        y[m] = p + br2[m];
    }
    float mx = y[0];
#pragma unroll
    for (int m = 1; m < MM; ++m) mx = fmaxf(mx, y[m]);
    float ssum = 0.f;
#pragma unroll
    for (int m = 0; m < MM; ++m) { y[m] = expf(y[m] - mx); ssum += y[m]; }
    if (lane == 0) {
        float inv = 1.f / ssum;
#pragma unroll
        for (int m = 0; m < MM; ++m) g_gates[row * MM + m] = y[m] * inv;
    }
}

// ---------------- K2: Hebbian conn prefix ----------------
__global__ void conn_kernel(const float* __restrict__ conn0) {
    extern __shared__ float gs[];   // NB*SL*MM floats
    int tid = threadIdx.x;          // 64 threads
    for (int i = tid; i < NB * SL * MM; i += 64) gs[i] = g_gates[i];
    __syncthreads();
    int i = tid >> 3, j = tid & 7;
    float c = conn0[tid];
    for (int t = 0; t < SL; ++t) {
        g_conn[t * 64 + tid] = c;
        float v = 0.f;
#pragma unroll
        for (int b = 0; b < NB; ++b)
            v += gs[(b * SL + t) * MM + i] * gs[(b * SL + t) * MM + j];
        c += LAMBDA * v;
    }
}

// ---------------- K3: scan — round-10 structure + light score fusion ----------------
// SMEM float offsets
#define XW3   0        // 16384 (own module eW3)
#define XMEM  16384    // 2048
#define XB1   18432
#define XE1G  18560
#define XE1B  18688
#define XB2   18816
#define XE2G  18944
#define XE2B  19072
#define XB3   19200
#define XLNG  19328
#define XLNB  19456
#define XCUR  19584
#define XCOMB 19712
#define XV1   19840
#define XV2   19968
#define XAGG  20096
#define XSOWN 20224
#define XST0  20352    // 1024 (states, parity 0)
#define XST1  21376    // 1024 (states, parity 1)
#define XSA   22400    // 1024
#define XSB   23424    // 1024
#define XPART 24448    // 2048
#define XATR0 26496    // 16 (read scores, parity 0)
#define XATR1 26512    // 16 (read scores, parity 1)
#define XATTW 26528    // 16 (write-attention scores)
#define XG    26544    // 8
#define XCR   26552    // 8
#define XCG   26560    // 8
#define XMB   26568    // 8 (3 mbarriers: +0,+2,+4)
#define XWM   26576    // 16384 (Wmsg)
#define XTOT  42960
#define SCAN_SMEM_BYTES (XTOT * 4)
#define EXCH_BYTES 4096u   /* 8 ranks x 128 floats */

__device__ __forceinline__ float red16(const float* sm, int tid) {  // tid < 128
    float v = 0.f;
#pragma unroll
    for (int q = 0; q < 16; ++q) v += sm[XPART + q * 128 + tid];
    return v;
}

// warp-replicated LN stats of a 128-vector at sm[off] -> mean, inv
__device__ __forceinline__ void ln_stats(const float* sm, int off, int lane,
                                         float& mean, float& inv) {
    float a0 = sm[off + lane], a1 = sm[off + 32 + lane];
    float a2 = sm[off + 64 + lane], a3 = sm[off + 96 + lane];
    float s1 = wsum(a0 + a1 + a2 + a3);
    float s2 = wsum(fmaf(a0, a0, fmaf(a1, a1, fmaf(a2, a2, a3 * a3))));
    mean = s1 * (1.f / 128.f);
    float var = s2 * (1.f / 128.f) - mean * mean;
    inv = rsqrtf(var + 1e-5f);
}

// push value v into slot (rank*128 + d) of buffer `dstoff` in ALL 8 cluster CTAs,
// signaling each peer's mbarrier via st.async transaction bytes.
__device__ __forceinline__ void push_async(float* sm, int dstoff, int mboff,
                                           int rank, int d, float v) {
    unsigned dst0 = smaddr(sm + dstoff + rank * 128 + d);
    unsigned mb0 = smaddr(sm + mboff);
    unsigned vi = __float_as_uint(v);
#pragma unroll
    for (int r = 0; r < MM; ++r) {
        unsigned dst, mb;
        asm("mapa.shared::cluster.u32 %0, %1, %2;" : "=r"(dst) : "r"(dst0), "r"(r));
        asm("mapa.shared::cluster.u32 %0, %1, %2;" : "=r"(mb) : "r"(mb0), "r"(r));
        asm volatile("st.async.shared::cluster.mbarrier::complete_tx::bytes.b32 [%0], %1, [%2];"
                     :: "r"(dst), "r"(vi), "r"(mb) : "memory");
    }
}

__device__ __forceinline__ void mbar_wait(float* sm, int mboff, unsigned parity) {
    unsigned mb = smaddr(sm + mboff);
    asm volatile(
        "{\n\t.reg .pred P;\n"
        "W%=:\n\t"
        "mbarrier.try_wait.parity.acquire.cluster.shared::cta.b64 P, [%0], %1, 0x989680;\n\t"
        "@P bra.uni D%=;\n\t"
        "bra.uni W%=;\n"
        "D%=:\n\t}"
        :: "r"(mb), "r"(parity) : "memory");
}

__global__ void __launch_bounds__(512, 1) __cluster_dims__(MM, 1, 1) scan_kernel(
    const float* __restrict__ mem0, const float* __restrict__ Wmsg,
    const float* __restrict__ ln_g, const float* __restrict__ ln_b,
    const float* __restrict__ eW1, const float* __restrict__ eb1,
    const float* __restrict__ e1g, const float* __restrict__ e1b,
    const float* __restrict__ eW2, const float* __restrict__ eb2,
    const float* __restrict__ e2g, const float* __restrict__ e2b,
    const float* __restrict__ eW3, const float* __restrict__ eb3) {
    extern __shared__ float sm[];
    cg::cluster_group cluster = cg::this_cluster();
    int tid = threadIdx.x;
    int rank = (int)cluster.block_rank();        // module index
    int b = blockIdx.x >> 3;                     // batch index
    int warp = tid >> 5, lane = tid & 31;        // warp == k-group (16)

    // register-resident W1, W2: thread (kq=warp, jq=lane) holds its 8 weight quads
    float4 w1r[8], w2r[8];
    {
        const float4* W1g = reinterpret_cast<const float4*>(eW1 + (size_t)rank * 16384);
        const float4* W2g = reinterpret_cast<const float4*>(eW2 + (size_t)rank * 16384);
        int base = (warp * 8) * 32 + lane;
#pragma unroll
        for (int k = 0; k < 8; ++k) {
            w1r[k] = W1g[base + k * 32];
            w2r[k] = W2g[base + k * 32];
        }
        const float* w3 = eW3 + (size_t)rank * 16384;
        for (int i = tid; i < 16384; i += 512) {
            sm[XW3 + i] = w3[i];
            sm[XWM + i] = Wmsg[i];
        }
        for (int i = tid; i < 2048; i += 512) sm[XMEM + i] = mem0[i];
        if (tid < 128) {
            sm[XB1 + tid]  = eb1[rank * 128 + tid];
            sm[XE1G + tid] = e1g[rank * 128 + tid];
            sm[XE1B + tid] = e1b[rank * 128 + tid];
            sm[XB2 + tid]  = eb2[rank * 128 + tid];
            sm[XE2G + tid] = e2g[rank * 128 + tid];
            sm[XE2B + tid] = e2b[rank * 128 + tid];
            sm[XB3 + tid]  = eb3[rank * 128 + tid];
            sm[XLNG + tid] = ln_g[tid];
            sm[XLNB + tid] = ln_b[tid];
        }
        // t=0 step inputs
        if (tid < 128) sm[XCUR + tid] = g_x[(b * SL) * DD + tid];
        else if (tid < 136) sm[XG + tid - 128] = g_gates[(b * SL) * MM + (tid - 128)];
        else if (tid < 144) sm[XCR + tid - 136] = g_conn[rank * 8 + (tid - 136)];
        if (tid == 0) {
#pragma unroll
            for (int q = 0; q < 3; ++q) {
                unsigned mb = smaddr(sm + XMB + 2 * q);
                asm volatile("mbarrier.init.shared.b64 [%0], %1;" :: "r"(mb), "r"(1u) : "memory");
            }
        }
    }
    cluster.sync();   // all SMEM + mbarriers ready cluster-wide

    // prologue: read-attention scores for t=0 (warp w -> slot w)
    {
        float pp = 0.f;
#pragma unroll
        for (int c = 0; c < 4; ++c) {
            int k = lane + 32 * c;
            pp = fmaf(sm[XCUR + k], sm[XMEM + warp * DD + k], pp);
        }
        pp = wsum(pp);
        if (lane == 0) sm[XATR0 + warp] = pp * SCALE_D;
    }
    __syncthreads();

    float4* part4 = reinterpret_cast<float4*>(sm + XPART);
    const float4* Wm4 = reinterpret_cast<const float4*>(sm + XWM) + (warp * 8) * 32 + lane;
    const float4* W34 = reinterpret_cast<const float4*>(sm + XW3) + (warp * 8) * 32 + lane;

    for (int t = 0; t < SL; ++t) {
        int xst = (t & 1) ? XST1 : XST0;
        int xatr = (t & 1) ? XATR1 : XATR0;
        int nxatr = (t & 1) ? XATR0 : XATR1;
        unsigned par = (unsigned)(t & 1);
        if (tid == 0) {
#pragma unroll
            for (int q = 0; q < 3; ++q) {
                unsigned mb = smaddr(sm + XMB + 2 * q);
                asm volatile("mbarrier.arrive.expect_tx.shared.b64 _, [%0], %1;"
                             :: "r"(mb), "r"(EXCH_BYTES) : "memory");
            }
        } else if (tid >= 32 && tid < 40) sm[XCG + tid - 32] = sm[XCR + tid - 32] * sm[XG + tid - 32];
        // prefetch t+1 inputs into regs
        float pref = 0.f;
        if (t < SL - 1) {
            if (tid < 128) pref = g_x[(b * SL + t + 1) * DD + tid];
            else if (tid < 136) pref = g_gates[(b * SL + t + 1) * MM + (tid - 128)];
            else if (tid < 144) pref = g_conn[(t + 1) * 64 + rank * 8 + (tid - 136)];
        }

        // A: comb = cur + retrieved (softmax over precomputed scores), warps 0-3
        if (tid < 128) {
            float vv = (lane < NM) ? sm[xatr + lane] : -1e30f;
            float mx = wmaxf(vv);
            float e = (lane < NM) ? expf(vv - mx) : 0.f;
            float ss = wsum(e);
            float aval = e / ss;
            float r = 0.f;
#pragma unroll
            for (int n = 0; n < NM; ++n) {
                float an = __shfl_sync(0xffffffffu, aval, n);
                r = fmaf(an, sm[XMEM + n * DD + tid], r);
            }
            sm[XCOMB + tid] = sm[XCUR + tid] + r;
        }
        __syncthreads();                                              // B1

        // L1: inline LN(comb) -> matvec with w1r
        {
            float mean, inv;
            ln_stats(sm, XCOMB, lane, mean, inv);
            float4 acc = make_float4(0.f, 0.f, 0.f, 0.f);
#pragma unroll
            for (int k = 0; k < 8; ++k) {
                int idx = warp * 8 + k;
                float xv = (sm[XCOMB + idx] - mean) * inv * sm[XLNG + idx] + sm[XLNB + idx];
                float4 w = w1r[k];
                acc.x = fmaf(xv, w.x, acc.x); acc.y = fmaf(xv, w.y, acc.y);
                acc.z = fmaf(xv, w.z, acc.z); acc.w = fmaf(xv, w.w, acc.w);
            }
            part4[warp * 32 + lane] = acc;
        }
        __syncthreads();                                              // B2
        if (tid < 128) sm[XV1 + tid] = red16(sm, tid) + sm[XB1 + tid];
        __syncthreads();                                              // B3

        // L2: inline relu(LN(v1)) -> matvec with w2r
        {
            float mean, inv;
            ln_stats(sm, XV1, lane, mean, inv);
            float4 acc = make_float4(0.f, 0.f, 0.f, 0.f);
#pragma unroll
            for (int k = 0; k < 8; ++k) {
                int idx = warp * 8 + k;
                float xv = fmaxf((sm[XV1 + idx] - mean) * inv * sm[XE1G + idx] + sm[XE1B + idx], 0.f);
                float4 w = w2r[k];
                acc.x = fmaf(xv, w.x, acc.x); acc.y = fmaf(xv, w.y, acc.y);
                acc.z = fmaf(xv, w.z, acc.z); acc.w = fmaf(xv, w.w, acc.w);
            }
            part4[warp * 32 + lane] = acc;
        }
        __syncthreads();                                              // B4
        if (tid < 128) sm[XV2 + tid] = red16(sm, tid) + sm[XB2 + tid];
        __syncthreads();                                              // B5

        // L3: inline relu(LN(v2)) -> matvec with SMEM W3
        {
            float mean, inv;
            ln_stats(sm, XV2, lane, mean, inv);
            float4 acc = make_float4(0.f, 0.f, 0.f, 0.f);
#pragma unroll
            for (int k = 0; k < 8; ++k) {
                int idx = warp * 8 + k;
                float xv = fmaxf((sm[XV2 + idx] - mean) * inv * sm[XE2G + idx] + sm[XE2B + idx], 0.f);
                float4 w = W34[k * 32];
                acc.x = fmaf(xv, w.x, acc.x); acc.y = fmaf(xv, w.y, acc.y);
                acc.z = fmaf(xv, w.z, acc.z); acc.w = fmaf(xv, w.w, acc.w);
            }
            part4[warp * 32 + lane] = acc;
        }
        __syncthreads();                                              // B6

        // P1: s reduce + st.async push to all ranks' XST[parity]
        if (tid < 128) {
            float v = red16(sm, tid) + sm[XB3 + tid];
            sm[XSOWN + tid] = v;
            push_async(sm, xst, XMB + 0, rank, tid, v);
        }
        mbar_wait(sm, XMB + 0, par);                                  // E1

        // MP1: warp-local msg (lanes<8) + shfl, matvec with Wmsg (SMEM)
        {
            float msgv = 0.f;
            if (lane < 8) {
                int k = warp * 8 + lane;
#pragma unroll
                for (int jm = 0; jm < MM; ++jm)
                    msgv = fmaf(sm[XCG + jm], sm[xst + jm * 128 + k], msgv);
            }
            float4 acc = make_float4(0.f, 0.f, 0.f, 0.f);
#pragma unroll
            for (int k = 0; k < 8; ++k) {
                float xv = __shfl_sync(0xffffffffu, msgv, k);
                float4 w = Wm4[k * 32];
                acc.x = fmaf(xv, w.x, acc.x); acc.y = fmaf(xv, w.y, acc.y);
                acc.z = fmaf(xv, w.z, acc.z); acc.w = fmaf(xv, w.w, acc.w);
            }
            part4[warp * 32 + lane] = acc;
        }
        __syncthreads();                                              // B7

        // P2: y1 reduce + s update + push XSA
        if (tid < 128) {
            float y = red16(sm, tid);
            float ns = sm[XSOWN + tid] + fmaxf(y, 0.f);
            sm[XSOWN + tid] = ns;
            push_async(sm, XSA, XMB + 2, rank, tid, ns);
        }
        mbar_wait(sm, XMB + 2, par);                                  // E2

        // MP2 + park cur(t+1) into XCUR (cur(t) last read in phase A)
        {
            if (tid < 128 && t < SL - 1) sm[XCUR + tid] = pref;
            float msgv = 0.f;
            if (lane < 8) {
                int k = warp * 8 + lane;
#pragma unroll
                for (int jm = 0; jm < MM; ++jm)
                    msgv = fmaf(sm[XCG + jm], sm[XSA + jm * 128 + k], msgv);
            }
            float4 acc = make_float4(0.f, 0.f, 0.f, 0.f);
#pragma unroll
            for (int k = 0; k < 8; ++k) {
                float xv = __shfl_sync(0xffffffffu, msgv, k);
                float4 w = Wm4[k * 32];
                acc.x = fmaf(xv, w.x, acc.x); acc.y = fmaf(xv, w.y, acc.y);
                acc.z = fmaf(xv, w.z, acc.z); acc.w = fmaf(xv, w.w, acc.w);
            }
            part4[warp * 32 + lane] = acc;
        }
        __syncthreads();                                              // B8

        // P3: y2 reduce + push final s to XSB
        if (tid < 128) {
            float y = red16(sm, tid);
            float v = sm[XSOWN + tid] + fmaxf(y, 0.f);
            push_async(sm, XSB, XMB + 4, rank, tid, v);
        }
        mbar_wait(sm, XMB + 4, par);                                  // E3

        // agg + g_out (round-10 form)
        if (tid < 128) {
            float a = 0.f, ms = 0.f;
#pragma unroll
            for (int m = 0; m < MM; ++m) {
                a = fmaf(sm[XG + m], sm[xst + m * 128 + tid], a);
                ms += sm[XSB + m * 128 + tid];
            }
            float agg = a + 0.125f * ms;
            sm[XAGG + tid] = agg;
            if (rank == 0) g_out[(b * SL + t) * DD + tid] = agg;
        }
        __syncthreads();                                              // B9

        // write-attention scores: warp w -> XATTW[w]
        {
            float p = 0.f;
#pragma unroll
            for (int c = 0; c < 4; ++c) {
                int k = lane + 32 * c;
                p = fmaf(sm[XAGG + k], sm[XMEM + warp * DD + k], p);
            }
            p = wsum(p);
            if (lane == 0) sm[XATTW + warp] = p * SCALE_D;
        }
        __syncthreads();                                              // B10

        // TAIL: mem update (warp n owns row n) + fused next-step read score
        if (t < SL - 1) {
            float vv = (lane < NM) ? sm[XATTW + lane] : -1e30f;
            float mx = wmaxf(vv);
            float e = (lane < NM) ? expf(vv - mx) : 0.f;
            float ss = wsum(e);
            float aval = e / ss;
            float wn = __shfl_sync(0xffffffffu, aval, warp);
            float p = 0.f;
#pragma unroll
            for (int c = 0; c < 4; ++c) {
                int k = lane + 32 * c;
                float nm = fmaf(wn, sm[XAGG + k], sm[XMEM + warp * DD + k]);
                sm[XMEM + warp * DD + k] = nm;
                p = fmaf(sm[XCUR + k], nm, p);   // XCUR already holds cur(t+1)
            }
            p = wsum(p);
            if (lane == 0) sm[nxatr + warp] = p * SCALE_D;
            if (tid >= 128 && tid < 136) sm[XG + tid - 128] = pref;
            else if (tid >= 136 && tid < 144) sm[XCR + tid - 136] = pref;
        }
        __syncthreads();                                              // B11
    }
}

// ---------------- K4: QKV projections (split over blockIdx.y) ----------------
__global__ void qkv_kernel(const float* __restrict__ Wq, const float* __restrict__ Wk,
                           const float* __restrict__ Wv) {
    __shared__ float xs[32 * 128];
    int tid = threadIdx.x;
    int rowbase = blockIdx.x * 32;
    for (int idx = tid; idx < 4096; idx += 256) xs[idx] = g_out[rowbase * 128 + idx];
    __syncthreads();
    int rh = tid >> 7, jj = tid & 127;
    int w = blockIdx.y;
    const float* W = (w == 0) ? Wq : ((w == 1) ? Wk : Wv);
    float* O = (w == 0) ? g_q : ((w == 1) ? g_k : g_v);
    float acc[16];
#pragma unroll
    for (int r = 0; r < 16; ++r) acc[r] = 0.f;
    for (int k = 0; k < 128; ++k) {
        float wv = W[k * 128 + jj];
#pragma unroll
        for (int r = 0; r < 16; ++r) acc[r] = fmaf(xs[(rh * 16 + r) * 128 + k], wv, acc[r]);
    }
    int h = jj >> 5, dh = jj & 31;
#pragma unroll
    for (int r = 0; r < 16; ++r) {
        int row = rowbase + rh * 16 + r;
        int bb = row >> 9, s = row & 511;
        O[((bb * 4 + h) * SL + s) * 32 + dh] = acc[r];
    }
}

// ---------------- K5: sparse attention ----------------
__global__ void __launch_bounds__(256) attn_kernel() {
    extern __shared__ float ash[];
    float* kt = ash;              // 16384
    float* vt = ash + 16384;      // 16384
    float* cp = ash + 32768;      // 8192
    int tid = threadIdx.x, warp = tid >> 5, lane = tid & 31;
    int bh = blockIdx.x;
    const float* kb = g_k + bh * SL * 32;
    const float* vb = g_v + bh * SL * 32;
    for (int idx = tid; idx < SL * 32; idx += 256) {
        int n = idx >> 5, dh = idx & 31, sw = (dh + n) & 31;
        kt[n * 32 + sw] = kb[idx];
        vt[n * 32 + sw] = vb[idx];
    }
    __syncthreads();

    int qrow = blockIdx.y * 8 + warp;
    float qv = g_q[bh * SL * 32 + qrow * 32 + lane];
    float sc[16];
#pragma unroll
    for (int c = 0; c < 16; ++c) sc[c] = 0.f;
    for (int dh = 0; dh < 32; ++dh) {
        float qd = __shfl_sync(0xffffffffu, qv, dh);
#pragma unroll
        for (int c = 0; c < 16; ++c) {
            int n = c * 32 + lane;
            sc[c] = fmaf(qd, kt[n * 32 + ((dh + n) & 31)], sc[c]);
        }
    }
#pragma unroll
    for (int c = 0; c < 16; ++c) sc[c] *= SCALE_DH;

    unsigned eu[16];
#pragma unroll
    for (int c = 0; c < 16; ++c) {
        unsigned u = __float_as_uint(sc[c]);
        eu[c] = (u & 0x80000000u) ? ~u : (u | 0x80000000u);
    }
    unsigned thr = 0;
    for (int bit = 31; bit >= 0; --bit) {
        unsigned cand = thr | (1u << bit);
        int cnt = 0;
#pragma unroll
        for (int c = 0; c < 16; ++c) cnt += (eu[c] >= cand) ? 1 : 0;
        cnt = wsumi(cnt);
        if (cnt >= KK) thr = cand;
    }

    float mloc = -1e30f;
#pragma unroll
    for (int c = 0; c < 16; ++c) mloc = fmaxf(mloc, sc[c]);
    float mx = wmaxf(mloc);
    float ssum = 0.f;
#pragma unroll
    for (int c = 0; c < 16; ++c) ssum += (eu[c] >= thr) ? expf(sc[c] - mx) : 0.f;
    ssum = wsum(ssum);
    float inv = 1.f / ssum;

    float cx[32];
#pragma unroll
    for (int dh = 0; dh < 32; ++dh) cx[dh] = 0.f;
#pragma unroll 1
    for (int c = 0; c < 16; ++c) {
        float a = (eu[c] >= thr) ? expf(sc[c] - mx) * inv : 0.f;
        int n = c * 32 + lane;
#pragma unroll
        for (int dh = 0; dh < 32; ++dh)
            cx[dh] = fmaf(a, vt[n * 32 + ((dh + n) & 31)], cx[dh]);
    }

    float* cw = cp + warp * 1024;
#pragma unroll
    for (int dh = 0; dh < 32; ++dh) cw[lane * 32 + ((dh + lane) & 31)] = cx[dh];
    __syncwarp();
    float tot = 0.f;
#pragma unroll
    for (int src = 0; src < 32; ++src) tot += cw[src * 32 + ((lane + src) & 31)];
    int bb = bh >> 2, h = bh & 3;
    g_ctx[(bb * SL + qrow) * DD + h * 32 + lane] = tot;
}

// ---------------- K6: small 128x128 GEMMs ----------------
__global__ void gemm128_kernel(const float* __restrict__ W, const float* __restrict__ bias,
                               int mode) {
    __shared__ float xs[32 * 128];
    const float* in = mode ? g_out : g_ctx;
    float* out = mode ? g_d1 : g_out;
    int tid = threadIdx.x;
    int rowbase = blockIdx.x * 32;
    for (int idx = tid; idx < 4096; idx += 256) xs[idx] = in[rowbase * 128 + idx];
    __syncthreads();
    int rh = tid >> 7, jj = tid & 127;
    float acc[16];
#pragma unroll
    for (int r = 0; r < 16; ++r) acc[r] = 0.f;
    for (int k = 0; k < 128; ++k) {
        float wv = W[k * 128 + jj];
#pragma unroll
        for (int r = 0; r < 16; ++r) acc[r] = fmaf(xs[(rh * 16 + r) * 128 + k], wv, acc[r]);
    }
    float bb = mode ? bias[jj] : 0.f;
#pragma unroll
    for (int r = 0; r < 16; ++r) {
        float v = acc[r] + bb;
        if (mode) v = fmaxf(v, 0.f);
        out[(rowbase + rh * 16 + r) * 128 + jj] = v;
    }
}

// ---------------- K7: decoder [2048,128]@[128,32000] with f32x2 FMA ----------------
__global__ void __launch_bounds__(256) decoder_kernel(const float* __restrict__ Wd2,
                                                      const float* __restrict__ bd2,
                                                      float* __restrict__ out) {
    extern __shared__ float At[];   // 128*132 transposed A tile
    int tid = threadIdx.x;
    int rowbase = blockIdx.x * 128;
    for (int idx = tid; idx < 16384; idx += 256) {
        int r = idx >> 7, k = idx & 127;
        At[k * 132 + r] = g_d1[(rowbase + r) * 128 + k];
    }
    __syncthreads();
    int j = blockIdx.y * 64 + (tid & 63);
    int rq = tid >> 6;
    unsigned long long acc2[16];
#pragma unroll
    for (int i = 0; i < 16; ++i) acc2[i] = 0ull;
    const float* Bp = Wd2 + j;
    for (int k = 0; k < 128; ++k) {
        float w = Bp[(size_t)k * VOCAB];
        unsigned long long wp;
        asm("mov.b64 %0, {%1, %1};" : "=l"(wp) : "f"(w));
        const ulonglong2* a2 = reinterpret_cast<const ulonglong2*>(At + k * 132) + rq * 8;
#pragma unroll
        for (int rr = 0; rr < 8; ++rr) {
            ulonglong2 p = a2[rr];
            acc2[rr * 2]     = ffma2(p.x, wp, acc2[rr * 2]);
            acc2[rr * 2 + 1] = ffma2(p.y, wp, acc2[rr * 2 + 1]);
        }
    }
    float bb = bd2[j];
#pragma unroll
    for (int i = 0; i < 16; ++i) {
        float lo, hi;
        asm("mov.b64 {%0, %1}, %2;" : "=f"(lo), "=f"(hi) : "l"(acc2[i]));
        int row = rowbase + rq * 32 + i * 2;
        out[(size_t)row * VOCAB + j] = lo + bb;
        out[(size_t)(row + 1) * VOCAB + j] = hi + bb;
    }
}

// ---------------- launch ----------------
extern "C" void kernel_launch(void* const* d_in, const int* in_sizes, int n_in,
                              void* d_out, int out_size) {
    int off = (n_in > 30) ? 1 : 0;  // skip task_id if present
    const int*   seq  = (const int*)d_in[0];
    const float* emb  = (const float*)d_in[1 + off];
    const float* pos  = (const float*)d_in[2 + off];
    const float* Wr1  = (const float*)d_in[3 + off];
    const float* br1  = (const float*)d_in[4 + off];
    const float* Wr2  = (const float*)d_in[5 + off];
    const float* br2  = (const float*)d_in[6 + off];
    const float* ln_g = (const float*)d_in[7 + off];
    const float* ln_b = (const float*)d_in[8 + off];
    const float* eW1  = (const float*)d_in[9 + off];
    const float* eb1  = (const float*)d_in[10 + off];
    const float* e1g  = (const float*)d_in[11 + off];
    const float* e1b  = (const float*)d_in[12 + off];
    const float* eW2  = (const float*)d_in[13 + off];
    const float* eb2  = (const float*)d_in[14 + off];
    const float* e2g  = (const float*)d_in[15 + off];
    const float* e2b  = (const float*)d_in[16 + off];
    const float* eW3  = (const float*)d_in[17 + off];
    const float* eb3  = (const float*)d_in[18 + off];
    const float* mem0 = (const float*)d_in[19 + off];
    const float* Wmsg = (const float*)d_in[20 + off];
    const float* conn0= (const float*)d_in[21 + off];
    const float* Wq   = (const float*)d_in[22 + off];
    const float* Wk   = (const float*)d_in[23 + off];
    const float* Wv   = (const float*)d_in[24 + off];
    const float* Wo   = (const float*)d_in[25 + off];
    const float* Wd1  = (const float*)d_in[26 + off];
    const float* bd1  = (const float*)d_in[27 + off];
    const float* Wd2  = (const float*)d_in[28 + off];
    const float* bd2  = (const float*)d_in[29 + off];

    cudaFuncSetAttribute(conn_kernel, cudaFuncAttributeMaxDynamicSharedMemorySize, NB * SL * MM * 4);
    cudaFuncSetAttribute(scan_kernel, cudaFuncAttributeMaxDynamicSharedMemorySize, SCAN_SMEM_BYTES);
    cudaFuncSetAttribute(attn_kernel, cudaFuncAttributeMaxDynamicSharedMemorySize, 40960 * 4);
    cudaFuncSetAttribute(decoder_kernel, cudaFuncAttributeMaxDynamicSharedMemorySize, 128 * 132 * 4);

    embed_kernel<<<NB * SL, DD>>>(seq, emb, pos);
    gates_kernel<<<NB * SL / 8, 256>>>(Wr1, br1, Wr2, br2);
    conn_kernel<<<1, 64, NB * SL * MM * 4>>>(conn0);
    scan_kernel<<<NB * MM, 512, SCAN_SMEM_BYTES>>>(mem0, Wmsg, ln_g, ln_b,
                                                   eW1, eb1, e1g, e1b,
                                                   eW2, eb2, e2g, e2b, eW3, eb3);
    qkv_kernel<<<dim3(NB * SL / 32, 3), 256>>>(Wq, Wk, Wv);
    attn_kernel<<<dim3(NB * 4, SL / 8), 256, 40960 * 4>>>();
    gemm128_kernel<<<NB * SL / 32, 256>>>(Wo, bd1, 0);   // ctx @ Wo -> g_out
    gemm128_kernel<<<NB * SL / 32, 256>>>(Wd1, bd1, 1);  // relu(g_out @ Wd1 + bd1) -> g_d1
    decoder_kernel<<<dim3(NB * SL / 128, VOCAB / 64), 256, 128 * 132 * 4>>>(Wd2, bd2, (float*)d_out);
}

// round 15
// speedup vs baseline: 1.2393x; 1.0026x over previous
#include <cuda_runtime.h>
#include <cooperative_groups.h>
#include <math.h>

namespace cg = cooperative_groups;

#define NB 4
#define SL 512
#define VOCAB 32000
#define DD 128
#define MM 8
#define NM 16
#define KK 153
#define LAMBDA 0.0025f
#define SCALE_D 0.08838834764831845f   /* 1/sqrt(128) */
#define SCALE_DH 0.17677669529663687f  /* 1/sqrt(32)  */

// ---------------- scratch ----------------
__device__ float g_x[NB*SL*DD];
__device__ float g_gates[NB*SL*MM];
__device__ float g_conn[SL*MM*MM];
__device__ float g_out[NB*SL*DD];
__device__ float g_q[NB*4*SL*32];
__device__ float g_k[NB*4*SL*32];
__device__ float g_v[NB*4*SL*32];
__device__ float g_ctx[NB*SL*DD];
__device__ float g_d1[NB*SL*DD];

// ---------------- helpers ----------------
__device__ __forceinline__ float wsum(float v) {
#pragma unroll
    for (int o = 16; o; o >>= 1) v += __shfl_xor_sync(0xffffffffu, v, o);
    return v;
}
__device__ __forceinline__ float wmaxf(float v) {
#pragma unroll
    for (int o = 16; o; o >>= 1) v = fmaxf(v, __shfl_xor_sync(0xffffffffu, v, o));
    return v;
}
__device__ __forceinline__ int wsumi(int v) {
#pragma unroll
    for (int o = 16; o; o >>= 1) v += __shfl_xor_sync(0xffffffffu, v, o);
    return v;
}
__device__ __forceinline__ unsigned long long ffma2(unsigned long long a,
                                                    unsigned long long b,
                                                    unsigned long long c) {
    unsigned long long d;
    asm("fma.rn.f32x2 %0, %1, %2, %3;" : "=l"(d) : "l"(a), "l"(b), "l"(c));
    return d;
}
__device__ __forceinline__ unsigned smaddr(const void* p) {
    unsigned a;
    asm("{ .reg .u64 t; cvta.to.shared.u64 t, %1; cvt.u32.u64 %0, t; }" : "=r"(a) : "l"(p));
    return a;
}

// ---------------- K0: embedding + pos ----------------
__global__ void embed_kernel(const int* __restrict__ seq,
                             const float* __restrict__ emb,
                             const float* __restrict__ pos) {
    int row = blockIdx.x;            // b*SL + s
    int d = threadIdx.x;
    int s = row & (SL - 1);
    int tok = seq[row];
    g_x[row * DD + d] = emb[tok * DD + d] + pos[s * DD + d];
}

// ---------------- K1: router gates ----------------
__global__ void gates_kernel(const float* __restrict__ Wr1, const float* __restrict__ br1,
                             const float* __restrict__ Wr2, const float* __restrict__ br2) {
    __shared__ float xs[8][DD];
    int warp = threadIdx.x >> 5, lane = threadIdx.x & 31;
    int row = blockIdx.x * 8 + warp;
    const float* xr = g_x + row * DD;
#pragma unroll
    for (int c = 0; c < 4; ++c) xs[warp][lane + 32 * c] = xr[lane + 32 * c];
    __syncwarp();

    float acc[4] = {0.f, 0.f, 0.f, 0.f};
    for (int k = 0; k < DD; ++k) {
        float a = xs[warp][k];
#pragma unroll
        for (int c = 0; c < 4; ++c) acc[c] = fmaf(a, Wr1[k * DD + lane + 32 * c], acc[c]);
    }
    float t1[4];
#pragma unroll
    for (int c = 0; c < 4; ++c) t1[c] = fmaxf(acc[c] + br1[lane + 32 * c], 0.f);

    float y[MM];
#pragma unroll
    for (int m = 0; m < MM; ++m) {
        float p = 0.f;
#pragma unroll
        for (int c = 0; c < 4; ++c) p = fmaf(t1[c], Wr2[(lane + 32 * c) * MM + m], p);
        p = wsum(p);
        y[m] = p + br2[m];
    }
    float mx = y[0];
#pragma unroll
    for (int m = 1; m < MM; ++m) mx = fmaxf(mx, y[m]);
    float ssum = 0.f;
#pragma unroll
    for (int m = 0; m < MM; ++m) { y[m] = expf(y[m] - mx); ssum += y[m]; }
    if (lane == 0) {
        float inv = 1.f / ssum;
#pragma unroll
        for (int m = 0; m < MM; ++m) g_gates[row * MM + m] = y[m] * inv;
    }
}

// ---------------- K2: Hebbian conn prefix ----------------
__global__ void conn_kernel(const float* __restrict__ conn0) {
    extern __shared__ float gs[];   // NB*SL*MM floats
    int tid = threadIdx.x;          // 64 threads
    for (int i = tid; i < NB * SL * MM; i += 64) gs[i] = g_gates[i];
    __syncthreads();
    int i = tid >> 3, j = tid & 7;
    float c = conn0[tid];
    for (int t = 0; t < SL; ++t) {
        g_conn[t * 64 + tid] = c;
        float v = 0.f;
#pragma unroll
        for (int b = 0; b < NB; ++b)
            v += gs[(b * SL + t) * MM + i] * gs[(b * SL + t) * MM + j];
        c += LAMBDA * v;
    }
}

// ---------------- K3: scan — round-12 structure + contribution push ----------------
// SMEM float offsets
#define XW3   0        // 16384 (own module eW3)
#define XMEM  16384    // 2048
#define XB1   18432
#define XE1G  18560
#define XE1B  18688
#define XB2   18816
#define XE2G  18944
#define XE2B  19072
#define XB3   19200
#define XLNG  19328
#define XLNB  19456
#define XCUR  19584
#define XCOMB 19712
#define XV1   19840
#define XV2   19968
#define XAGG  20096
#define XSOWN 20224
#define XST0  20352    // 1024 (states, parity 0)
#define XST1  21376    // 1024 (states, parity 1)
#define XSA   22400    // 1024
#define XSB   23424    // 1024 (contributions)
#define XPART 24448    // 2048
#define XATR0 26496    // 16 (read scores, parity 0)
#define XATR1 26512    // 16 (read scores, parity 1)
#define XATTW 26528    // 16 (write-attention scores)
#define XG    26544    // 8
#define XCR   26552    // 8
#define XCG   26560    // 8
#define XMB   26568    // 8 (3 mbarriers: +0,+2,+4)
#define XWM   26576    // 16384 (Wmsg)
#define XTOT  42960
#define SCAN_SMEM_BYTES (XTOT * 4)
#define EXCH_BYTES 4096u   /* 8 ranks x 128 floats */

__device__ __forceinline__ float red16(const float* sm, int tid) {  // tid < 128
    float v = 0.f;
#pragma unroll
    for (int q = 0; q < 16; ++q) v += sm[XPART + q * 128 + tid];
    return v;
}

// warp-replicated LN stats of a 128-vector at sm[off] -> mean, inv
__device__ __forceinline__ void ln_stats(const float* sm, int off, int lane,
                                         float& mean, float& inv) {
    float a0 = sm[off + lane], a1 = sm[off + 32 + lane];
    float a2 = sm[off + 64 + lane], a3 = sm[off + 96 + lane];
    float s1 = wsum(a0 + a1 + a2 + a3);
    float s2 = wsum(fmaf(a0, a0, fmaf(a1, a1, fmaf(a2, a2, a3 * a3))));
    mean = s1 * (1.f / 128.f);
    float var = s2 * (1.f / 128.f) - mean * mean;
    inv = rsqrtf(var + 1e-5f);
}

// push value v into slot (rank*128 + d) of buffer `dstoff` in ALL 8 cluster CTAs,
// signaling each peer's mbarrier via st.async transaction bytes.
__device__ __forceinline__ void push_async(float* sm, int dstoff, int mboff,
                                           int rank, int d, float v) {
    unsigned dst0 = smaddr(sm + dstoff + rank * 128 + d);
    unsigned mb0 = smaddr(sm + mboff);
    unsigned vi = __float_as_uint(v);
#pragma unroll
    for (int r = 0; r < MM; ++r) {
        unsigned dst, mb;
        asm("mapa.shared::cluster.u32 %0, %1, %2;" : "=r"(dst) : "r"(dst0), "r"(r));
        asm("mapa.shared::cluster.u32 %0, %1, %2;" : "=r"(mb) : "r"(mb0), "r"(r));
        asm volatile("st.async.shared::cluster.mbarrier::complete_tx::bytes.b32 [%0], %1, [%2];"
                     :: "r"(dst), "r"(vi), "r"(mb) : "memory");
    }
}

__device__ __forceinline__ void mbar_wait(float* sm, int mboff, unsigned parity) {
    unsigned mb = smaddr(sm + mboff);
    asm volatile(
        "{\n\t.reg .pred P;\n"
        "W%=:\n\t"
        "mbarrier.try_wait.parity.acquire.cluster.shared::cta.b64 P, [%0], %1, 0x989680;\n\t"
        "@P bra.uni D%=;\n\t"
        "bra.uni W%=;\n"
        "D%=:\n\t}"
        :: "r"(mb), "r"(parity) : "memory");
}

__global__ void __launch_bounds__(512, 1) __cluster_dims__(MM, 1, 1) scan_kernel(
    const float* __restrict__ mem0, const float* __restrict__ Wmsg,
    const float* __restrict__ ln_g, const float* __restrict__ ln_b,
    const float* __restrict__ eW1, const float* __restrict__ eb1,
    const float* __restrict__ e1g, const float* __restrict__ e1b,
    const float* __restrict__ eW2, const float* __restrict__ eb2,
    const float* __restrict__ e2g, const float* __restrict__ e2b,
    const float* __restrict__ eW3, const float* __restrict__ eb3) {
    extern __shared__ float sm[];
    cg::cluster_group cluster = cg::this_cluster();
    int tid = threadIdx.x;
    int rank = (int)cluster.block_rank();        // module index
    int b = blockIdx.x >> 3;                     // batch index
    int warp = tid >> 5, lane = tid & 31;        // warp == k-group (16)

    // register-resident W1, W2: thread (kq=warp, jq=lane) holds its 8 weight quads
    float4 w1r[8], w2r[8];
    {
        const float4* W1g = reinterpret_cast<const float4*>(eW1 + (size_t)rank * 16384);
        const float4* W2g = reinterpret_cast<const float4*>(eW2 + (size_t)rank * 16384);
        int base = (warp * 8) * 32 + lane;
#pragma unroll
        for (int k = 0; k < 8; ++k) {
            w1r[k] = W1g[base + k * 32];
            w2r[k] = W2g[base + k * 32];
        }
        const float* w3 = eW3 + (size_t)rank * 16384;
        for (int i = tid; i < 16384; i += 512) {
            sm[XW3 + i] = w3[i];
            sm[XWM + i] = Wmsg[i];
        }
        for (int i = tid; i < 2048; i += 512) sm[XMEM + i] = mem0[i];
        if (tid < 128) {
            sm[XB1 + tid]  = eb1[rank * 128 + tid];
            sm[XE1G + tid] = e1g[rank * 128 + tid];
            sm[XE1B + tid] = e1b[rank * 128 + tid];
            sm[XB2 + tid]  = eb2[rank * 128 + tid];
            sm[XE2G + tid] = e2g[rank * 128 + tid];
            sm[XE2B + tid] = e2b[rank * 128 + tid];
            sm[XB3 + tid]  = eb3[rank * 128 + tid];
            sm[XLNG + tid] = ln_g[tid];
            sm[XLNB + tid] = ln_b[tid];
        }
        // t=0 step inputs
        if (tid < 128) sm[XCUR + tid] = g_x[(b * SL) * DD + tid];
        else if (tid < 136) sm[XG + tid - 128] = g_gates[(b * SL) * MM + (tid - 128)];
        else if (tid < 144) sm[XCR + tid - 136] = g_conn[rank * 8 + (tid - 136)];
        if (tid == 0) {
#pragma unroll
            for (int q = 0; q < 3; ++q) {
                unsigned mb = smaddr(sm + XMB + 2 * q);
                asm volatile("mbarrier.init.shared.b64 [%0], %1;" :: "r"(mb), "r"(1u) : "memory");
            }
        }
    }
    cluster.sync();   // all SMEM + mbarriers ready cluster-wide

    // prologue: read-attention scores for t=0 (warp w -> slot w)
    {
        float pp = 0.f;
#pragma unroll
        for (int c = 0; c < 4; ++c) {
            int k = lane + 32 * c;
            pp = fmaf(sm[XCUR + k], sm[XMEM + warp * DD + k], pp);
        }
        pp = wsum(pp);
        if (lane == 0) sm[XATR0 + warp] = pp * SCALE_D;
    }
    __syncthreads();

    float4* part4 = reinterpret_cast<float4*>(sm + XPART);
    const float4* Wm4 = reinterpret_cast<const float4*>(sm + XWM) + (warp * 8) * 32 + lane;
    const float4* W34 = reinterpret_cast<const float4*>(sm + XW3) + (warp * 8) * 32 + lane;

    for (int t = 0; t < SL; ++t) {
        int xst = (t & 1) ? XST1 : XST0;
        int xatr = (t & 1) ? XATR1 : XATR0;
        int nxatr = (t & 1) ? XATR0 : XATR1;
        unsigned par = (unsigned)(t & 1);
        if (tid == 0) {
#pragma unroll
            for (int q = 0; q < 3; ++q) {
                unsigned mb = smaddr(sm + XMB + 2 * q);
                asm volatile("mbarrier.arrive.expect_tx.shared.b64 _, [%0], %1;"
                             :: "r"(mb), "r"(EXCH_BYTES) : "memory");
            }
        } else if (tid >= 32 && tid < 40) sm[XCG + tid - 32] = sm[XCR + tid - 32] * sm[XG + tid - 32];
        // prefetch t+1 inputs into regs
        float pref = 0.f;
        if (t < SL - 1) {
            if (tid < 128) pref = g_x[(b * SL + t + 1) * DD + tid];
            else if (tid < 136) pref = g_gates[(b * SL + t + 1) * MM + (tid - 128)];
            else if (tid < 144) pref = g_conn[(t + 1) * 64 + rank * 8 + (tid - 136)];
        }

        // A: comb = cur + retrieved (softmax over precomputed scores), warps 0-3
        if (tid < 128) {
            float vv = (lane < NM) ? sm[xatr + lane] : -1e30f;
            float mx = wmaxf(vv);
            float e = (lane < NM) ? expf(vv - mx) : 0.f;
            float ss = wsum(e);
            float aval = e / ss;
            float r = 0.f;
#pragma unroll
            for (int n = 0; n < NM; ++n) {
                float an = __shfl_sync(0xffffffffu, aval, n);
                r = fmaf(an, sm[XMEM + n * DD + tid], r);
            }
            sm[XCOMB + tid] = sm[XCUR + tid] + r;
        }
        __syncthreads();                                              // B1

        // L1: inline LN(comb) -> matvec with w1r
        {
            float mean, inv;
            ln_stats(sm, XCOMB, lane, mean, inv);
            float4 acc = make_float4(0.f, 0.f, 0.f, 0.f);
#pragma unroll
            for (int k = 0; k < 8; ++k) {
                int idx = warp * 8 + k;
                float xv = (sm[XCOMB + idx] - mean) * inv * sm[XLNG + idx] + sm[XLNB + idx];
                float4 w = w1r[k];
                acc.x = fmaf(xv, w.x, acc.x); acc.y = fmaf(xv, w.y, acc.y);
                acc.z = fmaf(xv, w.z, acc.z); acc.w = fmaf(xv, w.w, acc.w);
            }
            part4[warp * 32 + lane] = acc;
        }
        __syncthreads();                                              // B2
        if (tid < 128) sm[XV1 + tid] = red16(sm, tid) + sm[XB1 + tid];
        __syncthreads();                                              // B3

        // L2: inline relu(LN(v1)) -> matvec with w2r
        {
            float mean, inv;
            ln_stats(sm, XV1, lane, mean, inv);
            float4 acc = make_float4(0.f, 0.f, 0.f, 0.f);
#pragma unroll
            for (int k = 0; k < 8; ++k) {
                int idx = warp * 8 + k;
                float xv = fmaxf((sm[XV1 + idx] - mean) * inv * sm[XE1G + idx] + sm[XE1B + idx], 0.f);
                float4 w = w2r[k];
                acc.x = fmaf(xv, w.x, acc.x); acc.y = fmaf(xv, w.y, acc.y);
                acc.z = fmaf(xv, w.z, acc.z); acc.w = fmaf(xv, w.w, acc.w);
            }
            part4[warp * 32 + lane] = acc;
        }
        __syncthreads();                                              // B4
        if (tid < 128) sm[XV2 + tid] = red16(sm, tid) + sm[XB2 + tid];
        __syncthreads();                                              // B5

        // L3: inline relu(LN(v2)) -> matvec with SMEM W3
        {
            float mean, inv;
            ln_stats(sm, XV2, lane, mean, inv);
            float4 acc = make_float4(0.f, 0.f, 0.f, 0.f);
#pragma unroll
            for (int k = 0; k < 8; ++k) {
                int idx = warp * 8 + k;
                float xv = fmaxf((sm[XV2 + idx] - mean) * inv * sm[XE2G + idx] + sm[XE2B + idx], 0.f);
                float4 w = W34[k * 32];
                acc.x = fmaf(xv, w.x, acc.x); acc.y = fmaf(xv, w.y, acc.y);
                acc.z = fmaf(xv, w.z, acc.z); acc.w = fmaf(xv, w.w, acc.w);
            }
            part4[warp * 32 + lane] = acc;
        }
        __syncthreads();                                              // B6

        // P1: s reduce + keep state copy (XCOMB dead after L1) + push states
        if (tid < 128) {
            float v = red16(sm, tid) + sm[XB3 + tid];
            sm[XSOWN + tid] = v;
            sm[XCOMB + tid] = v;                 // state copy for contribution push
            push_async(sm, xst, XMB + 0, rank, tid, v);
        }
        mbar_wait(sm, XMB + 0, par);                                  // E1

        // MP1: warp-local msg (lanes<8) + shfl, matvec with Wmsg (SMEM)
        {
            float msgv = 0.f;
            if (lane < 8) {
                int k = warp * 8 + lane;
#pragma unroll
                for (int jm = 0; jm < MM; ++jm)
                    msgv = fmaf(sm[XCG + jm], sm[xst + jm * 128 + k], msgv);
            }
            float4 acc = make_float4(0.f, 0.f, 0.f, 0.f);
#pragma unroll
            for (int k = 0; k < 8; ++k) {
                float xv = __shfl_sync(0xffffffffu, msgv, k);
                float4 w = Wm4[k * 32];
                acc.x = fmaf(xv, w.x, acc.x); acc.y = fmaf(xv, w.y, acc.y);
                acc.z = fmaf(xv, w.z, acc.z); acc.w = fmaf(xv, w.w, acc.w);
            }
            part4[warp * 32 + lane] = acc;
        }
        __syncthreads();                                              // B7

        // P2: y1 reduce + s update + push XSA
        if (tid < 128) {
            float y = red16(sm, tid);
            float ns = sm[XSOWN + tid] + fmaxf(y, 0.f);
            sm[XSOWN + tid] = ns;
            push_async(sm, XSA, XMB + 2, rank, tid, ns);
        }
        mbar_wait(sm, XMB + 2, par);                                  // E2

        // MP2 + park cur(t+1) into XCUR (cur(t) last read in phase A)
        {
            if (tid < 128 && t < SL - 1) sm[XCUR + tid] = pref;
            float msgv = 0.f;
            if (lane < 8) {
                int k = warp * 8 + lane;
#pragma unroll
                for (int jm = 0; jm < MM; ++jm)
                    msgv = fmaf(sm[XCG + jm], sm[XSA + jm * 128 + k], msgv);
            }
            float4 acc = make_float4(0.f, 0.f, 0.f, 0.f);
#pragma unroll
            for (int k = 0; k < 8; ++k) {
                float xv = __shfl_sync(0xffffffffu, msgv, k);
                float4 w = Wm4[k * 32];
                acc.x = fmaf(xv, w.x, acc.x); acc.y = fmaf(xv, w.y, acc.y);
                acc.z = fmaf(xv, w.z, acc.z); acc.w = fmaf(xv, w.w, acc.w);
            }
            part4[warp * 32 + lane] = acc;
        }
        __syncthreads();                                              // B8

        // P3: y2 reduce + push CONTRIBUTION g_rank*state + 0.125*s_final to XSB
        if (tid < 128) {
            float y = red16(sm, tid);
            float sfin = sm[XSOWN + tid] + fmaxf(y, 0.f);
            float contrib = fmaf(sm[XG + rank], sm[XCOMB + tid], 0.125f * sfin);
            push_async(sm, XSB, XMB + 4, rank, tid, contrib);
        }
        mbar_wait(sm, XMB + 4, par);                                  // E3

        // agg = sum of contributions
        if (tid < 128) {
            float agg = 0.f;
#pragma unroll
            for (int m = 0; m < MM; ++m) agg += sm[XSB + m * 128 + tid];
            sm[XAGG + tid] = agg;
            if (rank == 0) g_out[(b * SL + t) * DD + tid] = agg;
        }
        __syncthreads();                                              // B9

        if (t < SL - 1) {
            // write-attention scores: warp w -> XATTW[w]
            {
                float p = 0.f;
#pragma unroll
                for (int c = 0; c < 4; ++c) {
                    int k = lane + 32 * c;
                    p = fmaf(sm[XAGG + k], sm[XMEM + warp * DD + k], p);
                }
                p = wsum(p);
                if (lane == 0) sm[XATTW + warp] = p * SCALE_D;
            }
            __syncthreads();                                          // B10

            // TAIL: mem update (warp n owns row n) + fused next-step read score
            {
                float vv = (lane < NM) ? sm[XATTW + lane] : -1e30f;
                float mx = wmaxf(vv);
                float e = (lane < NM) ? expf(vv - mx) : 0.f;
                float ss = wsum(e);
                float aval = e / ss;
                float wn = __shfl_sync(0xffffffffu, aval, warp);
                float p = 0.f;
#pragma unroll
                for (int c = 0; c < 4; ++c) {
                    int k = lane + 32 * c;
                    float nm = fmaf(wn, sm[XAGG + k], sm[XMEM + warp * DD + k]);
                    sm[XMEM + warp * DD + k] = nm;
                    p = fmaf(sm[XCUR + k], nm, p);   // XCUR already holds cur(t+1)
                }
                p = wsum(p);
                if (lane == 0) sm[nxatr + warp] = p * SCALE_D;
                if (tid >= 128 && tid < 136) sm[XG + tid - 128] = pref;
                else if (tid >= 136 && tid < 144) sm[XCR + tid - 136] = pref;
            }
            __syncthreads();                                          // B11
        }
    }
}

// ---------------- K4: QKV projections (split over blockIdx.y) ----------------
__global__ void qkv_kernel(const float* __restrict__ Wq, const float* __restrict__ Wk,
                           const float* __restrict__ Wv) {
    __shared__ float xs[32 * 128];
    int tid = threadIdx.x;
    int rowbase = blockIdx.x * 32;
    for (int idx = tid; idx < 4096; idx += 256) xs[idx] = g_out[rowbase * 128 + idx];
    __syncthreads();
    int rh = tid >> 7, jj = tid & 127;
    int w = blockIdx.y;
    const float* W = (w == 0) ? Wq : ((w == 1) ? Wk : Wv);
    float* O = (w == 0) ? g_q : ((w == 1) ? g_k : g_v);
    float acc[16];
#pragma unroll
    for (int r = 0; r < 16; ++r) acc[r] = 0.f;
    for (int k = 0; k < 128; ++k) {
        float wv = W[k * 128 + jj];
#pragma unroll
        for (int r = 0; r < 16; ++r) acc[r] = fmaf(xs[(rh * 16 + r) * 128 + k], wv, acc[r]);
    }
    int h = jj >> 5, dh = jj & 31;
#pragma unroll
    for (int r = 0; r < 16; ++r) {
        int row = rowbase + rh * 16 + r;
        int bb = row >> 9, s = row & 511;
        O[((bb * 4 + h) * SL + s) * 32 + dh] = acc[r];
    }
}

// ---------------- K5: sparse attention ----------------
__global__ void __launch_bounds__(256) attn_kernel() {
    extern __shared__ float ash[];
    float* kt = ash;              // 16384
    float* vt = ash + 16384;      // 16384
    float* cp = ash + 32768;      // 8192
    int tid = threadIdx.x, warp = tid >> 5, lane = tid & 31;
    int bh = blockIdx.x;
    const float* kb = g_k + bh * SL * 32;
    const float* vb = g_v + bh * SL * 32;
    for (int idx = tid; idx < SL * 32; idx += 256) {
        int n = idx >> 5, dh = idx & 31, sw = (dh + n) & 31;
        kt[n * 32 + sw] = kb[idx];
        vt[n * 32 + sw] = vb[idx];
    }
    __syncthreads();

    int qrow = blockIdx.y * 8 + warp;
    float qv = g_q[bh * SL * 32 + qrow * 32 + lane];
    float sc[16];
#pragma unroll
    for (int c = 0; c < 16; ++c) sc[c] = 0.f;
    for (int dh = 0; dh < 32; ++dh) {
        float qd = __shfl_sync(0xffffffffu, qv, dh);
#pragma unroll
        for (int c = 0; c < 16; ++c) {
            int n = c * 32 + lane;
            sc[c] = fmaf(qd, kt[n * 32 + ((dh + n) & 31)], sc[c]);
        }
    }
#pragma unroll
    for (int c = 0; c < 16; ++c) sc[c] *= SCALE_DH;

    unsigned eu[16];
#pragma unroll
    for (int c = 0; c < 16; ++c) {
        unsigned u = __float_as_uint(sc[c]);
        eu[c] = (u & 0x80000000u) ? ~u : (u | 0x80000000u);
    }
    unsigned thr = 0;
    for (int bit = 31; bit >= 0; --bit) {
        unsigned cand = thr | (1u << bit);
        int cnt = 0;
#pragma unroll
        for (int c = 0; c < 16; ++c) cnt += (eu[c] >= cand) ? 1 : 0;
        cnt = wsumi(cnt);
        if (cnt >= KK) thr = cand;
    }

    float mloc = -1e30f;
#pragma unroll
    for (int c = 0; c < 16; ++c) mloc = fmaxf(mloc, sc[c]);
    float mx = wmaxf(mloc);
    float ssum = 0.f;
#pragma unroll
    for (int c = 0; c < 16; ++c) ssum += (eu[c] >= thr) ? expf(sc[c] - mx) : 0.f;
    ssum = wsum(ssum);
    float inv = 1.f / ssum;

    float cx[32];
#pragma unroll
    for (int dh = 0; dh < 32; ++dh) cx[dh] = 0.f;
#pragma unroll 1
    for (int c = 0; c < 16; ++c) {
        float a = (eu[c] >= thr) ? expf(sc[c] - mx) * inv : 0.f;
        int n = c * 32 + lane;
#pragma unroll
        for (int dh = 0; dh < 32; ++dh)
            cx[dh] = fmaf(a, vt[n * 32 + ((dh + n) & 31)], cx[dh]);
    }

    float* cw = cp + warp * 1024;
#pragma unroll
    for (int dh = 0; dh < 32; ++dh) cw[lane * 32 + ((dh + lane) & 31)] = cx[dh];
    __syncwarp();
    float tot = 0.f;
#pragma unroll
    for (int src = 0; src < 32; ++src) tot += cw[src * 32 + ((lane + src) & 31)];
    int bb = bh >> 2, h = bh & 3;
    g_ctx[(bb * SL + qrow) * DD + h * 32 + lane] = tot;
}

// ---------------- K6: small 128x128 GEMMs ----------------
__global__ void gemm128_kernel(const float* __restrict__ W, const float* __restrict__ bias,
                               int mode) {
    __shared__ float xs[32 * 128];
    const float* in = mode ? g_out : g_ctx;
    float* out = mode ? g_d1 : g_out;
    int tid = threadIdx.x;
    int rowbase = blockIdx.x * 32;
    for (int idx = tid; idx < 4096; idx += 256) xs[idx] = in[rowbase * 128 + idx];
    __syncthreads();
    int rh = tid >> 7, jj = tid & 127;
    float acc[16];
#pragma unroll
    for (int r = 0; r < 16; ++r) acc[r] = 0.f;
    for (int k = 0; k < 128; ++k) {
        float wv = W[k * 128 + jj];
#pragma unroll
        for (int r = 0; r < 16; ++r) acc[r] = fmaf(xs[(rh * 16 + r) * 128 + k], wv, acc[r]);
    }
    float bb = mode ? bias[jj] : 0.f;
#pragma unroll
    for (int r = 0; r < 16; ++r) {
        float v = acc[r] + bb;
        if (mode) v = fmaxf(v, 0.f);
        out[(rowbase + rh * 16 + r) * 128 + jj] = v;
    }
}

// ---------------- K7: decoder [2048,128]@[128,32000] with f32x2 FMA ----------------
__global__ void __launch_bounds__(256) decoder_kernel(const float* __restrict__ Wd2,
                                                      const float* __restrict__ bd2,
                                                      float* __restrict__ out) {
    extern __shared__ float At[];   // 128*132 transposed A tile
    int tid = threadIdx.x;
    int rowbase = blockIdx.x * 128;
    for (int idx = tid; idx < 16384; idx += 256) {
        int r = idx >> 7, k = idx & 127;
        At[k * 132 + r] = g_d1[(rowbase + r) * 128 + k];
    }
    __syncthreads();
    int j = blockIdx.y * 64 + (tid & 63);
    int rq = tid >> 6;
    unsigned long long acc2[16];
#pragma unroll
    for (int i = 0; i < 16; ++i) acc2[i] = 0ull;
    const float* Bp = Wd2 + j;
    for (int k = 0; k < 128; ++k) {
        float w = Bp[(size_t)k * VOCAB];
        unsigned long long wp;
        asm("mov.b64 %0, {%1, %1};" : "=l"(wp) : "f"(w));
        const ulonglong2* a2 = reinterpret_cast<const ulonglong2*>(At + k * 132) + rq * 8;
#pragma unroll
        for (int rr = 0; rr < 8; ++rr) {
            ulonglong2 p = a2[rr];
            acc2[rr * 2]     = ffma2(p.x, wp, acc2[rr * 2]);
            acc2[rr * 2 + 1] = ffma2(p.y, wp, acc2[rr * 2 + 1]);
        }
    }
    float bb = bd2[j];
#pragma unroll
    for (int i = 0; i < 16; ++i) {
        float lo, hi;
        asm("mov.b64 {%0, %1}, %2;" : "=f"(lo), "=f"(hi) : "l"(acc2[i]));
        int row = rowbase + rq * 32 + i * 2;
        out[(size_t)row * VOCAB + j] = lo + bb;
        out[(size_t)(row + 1) * VOCAB + j] = hi + bb;
    }
}

// ---------------- launch ----------------
extern "C" void kernel_launch(void* const* d_in, const int* in_sizes, int n_in,
                              void* d_out, int out_size) {
    int off = (n_in > 30) ? 1 : 0;  // skip task_id if present
    const int*   seq  = (const int*)d_in[0];
    const float* emb  = (const float*)d_in[1 + off];
    const float* pos  = (const float*)d_in[2 + off];
    const float* Wr1  = (const float*)d_in[3 + off];
    const float* br1  = (const float*)d_in[4 + off];
    const float* Wr2  = (const float*)d_in[5 + off];
    const float* br2  = (const float*)d_in[6 + off];
    const float* ln_g = (const float*)d_in[7 + off];
    const float* ln_b = (const float*)d_in[8 + off];
    const float* eW1  = (const float*)d_in[9 + off];
    const float* eb1  = (const float*)d_in[10 + off];
    const float* e1g  = (const float*)d_in[11 + off];
    const float* e1b  = (const float*)d_in[12 + off];
    const float* eW2  = (const float*)d_in[13 + off];
    const float* eb2  = (const float*)d_in[14 + off];
    const float* e2g  = (const float*)d_in[15 + off];
    const float* e2b  = (const float*)d_in[16 + off];
    const float* eW3  = (const float*)d_in[17 + off];
    const float* eb3  = (const float*)d_in[18 + off];
    const float* mem0 = (const float*)d_in[19 + off];
    const float* Wmsg = (const float*)d_in[20 + off];
    const float* conn0= (const float*)d_in[21 + off];
    const float* Wq   = (const float*)d_in[22 + off];
    const float* Wk   = (const float*)d_in[23 + off];
    const float* Wv   = (const float*)d_in[24 + off];
    const float* Wo   = (const float*)d_in[25 + off];
    const float* Wd1  = (const float*)d_in[26 + off];
    const float* bd1  = (const float*)d_in[27 + off];
    const float* Wd2  = (const float*)d_in[28 + off];
    const float* bd2  = (const float*)d_in[29 + off];

    cudaFuncSetAttribute(conn_kernel, cudaFuncAttributeMaxDynamicSharedMemorySize, NB * SL * MM * 4);
    cudaFuncSetAttribute(scan_kernel, cudaFuncAttributeMaxDynamicSharedMemorySize, SCAN_SMEM_BYTES);
    cudaFuncSetAttribute(attn_kernel, cudaFuncAttributeMaxDynamicSharedMemorySize, 40960 * 4);
    cudaFuncSetAttribute(decoder_kernel, cudaFuncAttributeMaxDynamicSharedMemorySize, 128 * 132 * 4);

    embed_kernel<<<NB * SL, DD>>>(seq, emb, pos);
    gates_kernel<<<NB * SL / 8, 256>>>(Wr1, br1, Wr2, br2);
    conn_kernel<<<1, 64, NB * SL * MM * 4>>>(conn0);
    scan_kernel<<<NB * MM, 512, SCAN_SMEM_BYTES>>>(mem0, Wmsg, ln_g, ln_b,
                                                   eW1, eb1, e1g, e1b,
                                                   eW2, eb2, e2g, e2b, eW3, eb3);
    qkv_kernel<<<dim3(NB * SL / 32, 3), 256>>>(Wq, Wk, Wv);
    attn_kernel<<<dim3(NB * 4, SL / 8), 256, 40960 * 4>>>();
    gemm128_kernel<<<NB * SL / 32, 256>>>(Wo, bd1, 0);   // ctx @ Wo -> g_out
    gemm128_kernel<<<NB * SL / 32, 256>>>(Wd1, bd1, 1);  // relu(g_out @ Wd1 + bd1) -> g_d1
    decoder_kernel<<<dim3(NB * SL / 128, VOCAB / 64), 256, 128 * 132 * 4>>>(Wd2, bd2, (float*)d_out);
}

// round 16
// speedup vs baseline: 1.2557x; 1.0132x over previous
#include <cuda_runtime.h>
#include <cooperative_groups.h>
#include <math.h>

namespace cg = cooperative_groups;

#define NB 4
#define SL 512
#define VOCAB 32000
#define DD 128
#define MM 8
#define NM 16
#define KK 153
#define LAMBDA 0.0025f
#define SCALE_D 0.08838834764831845f   /* 1/sqrt(128) */
#define SCALE_DH 0.17677669529663687f  /* 1/sqrt(32)  */

// ---------------- scratch ----------------
__device__ float g_x[NB*SL*DD];
__device__ float g_gates[NB*SL*MM];
__device__ float g_conn[SL*MM*MM];
__device__ float g_out[NB*SL*DD];
__device__ float g_q[NB*4*SL*32];
__device__ float g_k[NB*4*SL*32];
__device__ float g_v[NB*4*SL*32];
__device__ float g_ctx[NB*SL*DD];
__device__ float g_d1[NB*SL*DD];

// ---------------- helpers ----------------
__device__ __forceinline__ float wsum(float v) {
#pragma unroll
    for (int o = 16; o; o >>= 1) v += __shfl_xor_sync(0xffffffffu, v, o);
    return v;
}
__device__ __forceinline__ float wmaxf(float v) {
#pragma unroll
    for (int o = 16; o; o >>= 1) v = fmaxf(v, __shfl_xor_sync(0xffffffffu, v, o));
    return v;
}
__device__ __forceinline__ int rsumi(int v) {
    int r;
    asm volatile("redux.sync.add.u32 %0, %1, 0xffffffff;" : "=r"(r) : "r"(v));
    return r;
}
__device__ __forceinline__ unsigned long long ffma2(unsigned long long a,
                                                    unsigned long long b,
                                                    unsigned long long c) {
    unsigned long long d;
    asm("fma.rn.f32x2 %0, %1, %2, %3;" : "=l"(d) : "l"(a), "l"(b), "l"(c));
    return d;
}
__device__ __forceinline__ unsigned smaddr(const void* p) {
    unsigned a;
    asm("{ .reg .u64 t; cvta.to.shared.u64 t, %1; cvt.u32.u64 %0, t; }" : "=r"(a) : "l"(p));
    return a;
}

// ---------------- K1: embed + router gates (fused) ----------------
__global__ void gates_kernel(const int* __restrict__ seq,
                             const float* __restrict__ emb,
                             const float* __restrict__ pos,
                             const float* __restrict__ Wr1, const float* __restrict__ br1,
                             const float* __restrict__ Wr2, const float* __restrict__ br2) {
    __shared__ float xs[8][DD];
    int warp = threadIdx.x >> 5, lane = threadIdx.x & 31;
    int row = blockIdx.x * 8 + warp;
    int s = row & (SL - 1);
    int tok = seq[row];
#pragma unroll
    for (int c = 0; c < 4; ++c) {
        int k = lane + 32 * c;
        float xv = emb[tok * DD + k] + pos[s * DD + k];
        xs[warp][k] = xv;
        g_x[row * DD + k] = xv;
    }
    __syncwarp();

    float acc[4] = {0.f, 0.f, 0.f, 0.f};
    for (int k = 0; k < DD; ++k) {
        float a = xs[warp][k];
#pragma unroll
        for (int c = 0; c < 4; ++c) acc[c] = fmaf(a, Wr1[k * DD + lane + 32 * c], acc[c]);
    }
    float t1[4];
#pragma unroll
    for (int c = 0; c < 4; ++c) t1[c] = fmaxf(acc[c] + br1[lane + 32 * c], 0.f);

    float y[MM];
#pragma unroll
    for (int m = 0; m < MM; ++m) {
        float p = 0.f;
#pragma unroll
        for (int c = 0; c < 4; ++c) p = fmaf(t1[c], Wr2[(lane + 32 * c) * MM + m], p);
        p = wsum(p);
        y[m] = p + br2[m];
    }
    float mx = y[0];
#pragma unroll
    for (int m = 1; m < MM; ++m) mx = fmaxf(mx, y[m]);
    float ssum = 0.f;
#pragma unroll
    for (int m = 0; m < MM; ++m) { y[m] = expf(y[m] - mx); ssum += y[m]; }
    if (lane == 0) {
        float inv = 1.f / ssum;
#pragma unroll
        for (int m = 0; m < MM; ++m) g_gates[row * MM + m] = y[m] * inv;
    }
}

// ---------------- K2: Hebbian conn prefix ----------------
__global__ void conn_kernel(const float* __restrict__ conn0) {
    extern __shared__ float gs[];   // NB*SL*MM floats
    int tid = threadIdx.x;          // 64 threads
    for (int i = tid; i < NB * SL * MM; i += 64) gs[i] = g_gates[i];
    __syncthreads();
    int i = tid >> 3, j = tid & 7;
    float c = conn0[tid];
    for (int t = 0; t < SL; ++t) {
        g_conn[t * 64 + tid] = c;
        float v = 0.f;
#pragma unroll
        for (int b = 0; b < NB; ++b)
            v += gs[(b * SL + t) * MM + i] * gs[(b * SL + t) * MM + j];
        c += LAMBDA * v;
    }
}

// ---------------- K3: scan ----------------
// SMEM float offsets
#define XW3   0        // 16384 (own module eW3)
#define XMEM  16384    // 2048
#define XB1   18432
#define XE1G  18560
#define XE1B  18688
#define XB2   18816
#define XE2G  18944
#define XE2B  19072
#define XB3   19200
#define XLNG  19328
#define XLNB  19456
#define XCUR  19584
#define XCOMB 19712
#define XV1   19840
#define XV2   19968
#define XAGG  20096
#define XSOWN 20224
#define XST0  20352    // 1024 (states, parity 0)
#define XST1  21376    // 1024 (states, parity 1)
#define XSA   22400    // 1024
#define XSB   23424    // 1024 (contributions)
#define XPART 24448    // 2048
#define XATR0 26496    // 16 (read scores, parity 0)
#define XATR1 26512    // 16 (read scores, parity 1)
#define XATTW 26528    // 16 (write-attention scores)
#define XG    26544    // 8
#define XCR   26552    // 8
#define XCG   26560    // 8
#define XMB   26568    // 8 (3 mbarriers: +0,+2,+4)
#define XWM   26576    // 16384 (Wmsg)
#define XC1   42960    // 128 (sum_j ln_g[j]*W1[j][o])
#define XC2   43088    // 128 (sum_j ln_b[j]*W1[j][o])
#define XTOT  43216
#define SCAN_SMEM_BYTES (XTOT * 4)
#define EXCH_BYTES 4096u   /* 8 ranks x 128 floats */

__device__ __forceinline__ float red16(const float* sm, int tid) {  // tid < 128
    float v = 0.f;
#pragma unroll
    for (int q = 0; q < 16; ++q) v += sm[XPART + q * 128 + tid];
    return v;
}

// warp-replicated LN stats of a 128-vector at sm[off] -> mean, inv
__device__ __forceinline__ void ln_stats(const float* sm, int off, int lane,
                                         float& mean, float& inv) {
    float a0 = sm[off + lane], a1 = sm[off + 32 + lane];
    float a2 = sm[off + 64 + lane], a3 = sm[off + 96 + lane];
    float s1 = wsum(a0 + a1 + a2 + a3);
    float s2 = wsum(fmaf(a0, a0, fmaf(a1, a1, fmaf(a2, a2, a3 * a3))));
    mean = s1 * (1.f / 128.f);
    float var = s2 * (1.f / 128.f) - mean * mean;
    inv = rsqrtf(var + 1e-5f);
}

// push value v into slot (rank*128 + d) of buffer `dstoff` in ALL 8 cluster CTAs
__device__ __forceinline__ void push_async(float* sm, int dstoff, int mboff,
                                           int rank, int d, float v) {
    unsigned dst0 = smaddr(sm + dstoff + rank * 128 + d);
    unsigned mb0 = smaddr(sm + mboff);
    unsigned vi = __float_as_uint(v);
#pragma unroll
    for (int r = 0; r < MM; ++r) {
        unsigned dst, mb;
        asm("mapa.shared::cluster.u32 %0, %1, %2;" : "=r"(dst) : "r"(dst0), "r"(r));
        asm("mapa.shared::cluster.u32 %0, %1, %2;" : "=r"(mb) : "r"(mb0), "r"(r));
        asm volatile("st.async.shared::cluster.mbarrier::complete_tx::bytes.b32 [%0], %1, [%2];"
                     :: "r"(dst), "r"(vi), "r"(mb) : "memory");
    }
}

__device__ __forceinline__ void mbar_wait(float* sm, int mboff, unsigned parity) {
    unsigned mb = smaddr(sm + mboff);
    asm volatile(
        "{\n\t.reg .pred P;\n"
        "W%=:\n\t"
        "mbarrier.try_wait.parity.acquire.cluster.shared::cta.b64 P, [%0], %1, 0x989680;\n\t"
        "@P bra.uni D%=;\n\t"
        "bra.uni W%=;\n"
        "D%=:\n\t}"
        :: "r"(mb), "r"(parity) : "memory");
}

__global__ void __launch_bounds__(512, 1) __cluster_dims__(MM, 1, 1) scan_kernel(
    const float* __restrict__ mem0, const float* __restrict__ Wmsg,
    const float* __restrict__ ln_g, const float* __restrict__ ln_b,
    const float* __restrict__ eW1, const float* __restrict__ eb1,
    const float* __restrict__ e1g, const float* __restrict__ e1b,
    const float* __restrict__ eW2, const float* __restrict__ eb2,
    const float* __restrict__ e2g, const float* __restrict__ e2b,
    const float* __restrict__ eW3, const float* __restrict__ eb3) {
    extern __shared__ float sm[];
    cg::cluster_group cluster = cg::this_cluster();
    int tid = threadIdx.x;
    int rank = (int)cluster.block_rank();        // module index
    int b = blockIdx.x >> 3;                     // batch index
    int warp = tid >> 5, lane = tid & 31;        // warp == k-group (16)

    // register-resident W1, W2: thread (kq=warp, jq=lane) holds its 8 weight quads
    float4 w1r[8], w2r[8];
    {
        const float4* W1g = reinterpret_cast<const float4*>(eW1 + (size_t)rank * 16384);
        const float4* W2g = reinterpret_cast<const float4*>(eW2 + (size_t)rank * 16384);
        int base = (warp * 8) * 32 + lane;
#pragma unroll
        for (int k = 0; k < 8; ++k) {
            w1r[k] = W1g[base + k * 32];
            w2r[k] = W2g[base + k * 32];
        }
        const float* w3 = eW3 + (size_t)rank * 16384;
        for (int i = tid; i < 16384; i += 512) {
            sm[XW3 + i] = w3[i];
            sm[XWM + i] = Wmsg[i];
        }
        for (int i = tid; i < 2048; i += 512) sm[XMEM + i] = mem0[i];
        if (tid < 128) {
            sm[XB1 + tid]  = eb1[rank * 128 + tid];
            sm[XE1G + tid] = e1g[rank * 128 + tid];
            sm[XE1B + tid] = e1b[rank * 128 + tid];
            sm[XB2 + tid]  = eb2[rank * 128 + tid];
            sm[XE2G + tid] = e2g[rank * 128 + tid];
            sm[XE2B + tid] = e2b[rank * 128 + tid];
            sm[XB3 + tid]  = eb3[rank * 128 + tid];
            sm[XLNG + tid] = ln_g[tid];
            sm[XLNB + tid] = ln_b[tid];
        }
        // t=0 step inputs
        if (tid < 128) sm[XCUR + tid] = g_x[(b * SL) * DD + tid];
        else if (tid < 136) sm[XG + tid - 128] = g_gates[(b * SL) * MM + (tid - 128)];
        else if (tid < 144) sm[XCR + tid - 136] = g_conn[rank * 8 + (tid - 136)];
        if (tid == 0) {
#pragma unroll
            for (int q = 0; q < 3; ++q) {
                unsigned mb = smaddr(sm + XMB + 2 * q);
                asm volatile("mbarrier.init.shared.b64 [%0], %1;" :: "r"(mb), "r"(1u) : "memory");
            }
        }
    }
    cluster.sync();   // all SMEM + mbarriers ready cluster-wide

    float4* part4 = reinterpret_cast<float4*>(sm + XPART);
    float4* partB4 = reinterpret_cast<float4*>(sm + XSA);  // scratch during prologue
    const float4* Wm4 = reinterpret_cast<const float4*>(sm + XWM) + (warp * 8) * 32 + lane;
    const float4* W34 = reinterpret_cast<const float4*>(sm + XW3) + (warp * 8) * 32 + lane;

    // prologue 1: fold ln_g into w1r; build c1/c2 partials
    {
        float4 a2c = make_float4(0.f, 0.f, 0.f, 0.f);  // sum W1*ln_b
        float4 a1c = make_float4(0.f, 0.f, 0.f, 0.f);  // sum (W1*ln_g)
#pragma unroll
        for (int k = 0; k < 8; ++k) {
            int idx = warp * 8 + k;
            float lb = sm[XLNB + idx], lg = sm[XLNG + idx];
            a2c.x = fmaf(w1r[k].x, lb, a2c.x); a2c.y = fmaf(w1r[k].y, lb, a2c.y);
            a2c.z = fmaf(w1r[k].z, lb, a2c.z); a2c.w = fmaf(w1r[k].w, lb, a2c.w);
            w1r[k].x *= lg; w1r[k].y *= lg; w1r[k].z *= lg; w1r[k].w *= lg;
            a1c.x += w1r[k].x; a1c.y += w1r[k].y; a1c.z += w1r[k].z; a1c.w += w1r[k].w;
        }
        part4[warp * 32 + lane] = a2c;
        partB4[warp * 32 + lane] = a1c;
    }
    __syncthreads();
    if (tid < 128) {
        float s2c = 0.f, s1c = 0.f;
#pragma unroll
        for (int q = 0; q < 16; ++q) {
            s2c += sm[XPART + q * 128 + tid];
            s1c += sm[XSA + q * 128 + tid];
        }
        sm[XC2 + tid] = s2c;
        sm[XC1 + tid] = s1c;
    }
    // prologue 2: read-attention scores for t=0 (warp w -> slot w)
    {
        float pp = 0.f;
#pragma unroll
        for (int c = 0; c < 4; ++c) {
            int k = lane + 32 * c;
            pp = fmaf(sm[XCUR + k], sm[XMEM + warp * DD + k], pp);
        }
        pp = wsum(pp);
        if (lane == 0) sm[XATR0 + warp] = pp * SCALE_D;
    }
    __syncthreads();

    for (int t = 0; t < SL; ++t) {
        int xst = (t & 1) ? XST1 : XST0;
        int xatr = (t & 1) ? XATR1 : XATR0;
        int nxatr = (t & 1) ? XATR0 : XATR1;
        unsigned par = (unsigned)(t & 1);
        if (tid == 0) {
#pragma unroll
            for (int q = 0; q < 3; ++q) {
                unsigned mb = smaddr(sm + XMB + 2 * q);
                asm volatile("mbarrier.arrive.expect_tx.shared.b64 _, [%0], %1;"
                             :: "r"(mb), "r"(EXCH_BYTES) : "memory");
            }
        } else if (tid >= 32 && tid < 40) sm[XCG + tid - 32] = sm[XCR + tid - 32] * sm[XG + tid - 32];
        // prefetch t+1 inputs into regs
        float pref = 0.f;
        if (t < SL - 1) {
            if (tid < 128) pref = g_x[(b * SL + t + 1) * DD + tid];
            else if (tid < 136) pref = g_gates[(b * SL + t + 1) * MM + (tid - 128)];
            else if (tid < 144) pref = g_conn[(t + 1) * 64 + rank * 8 + (tid - 136)];
        }

        // A: comb = cur + retrieved (softmax over precomputed scores), warps 0-3
        if (tid < 128) {
            float vv = (lane < NM) ? sm[xatr + lane] : -1e30f;
            float mx = wmaxf(vv);
            float e = (lane < NM) ? expf(vv - mx) : 0.f;
            float ss = wsum(e);
            float aval = e / ss;
            float r = 0.f;
#pragma unroll
            for (int n = 0; n < NM; ++n) {
                float an = __shfl_sync(0xffffffffu, aval, n);
                r = fmaf(an, sm[XMEM + n * DD + tid], r);
            }
            sm[XCOMB + tid] = sm[XCUR + tid] + r;
        }
        __syncthreads();                                              // B1

        // L1: matvec on RAW comb with ln_g-folded w1r; warps 0-3 compute stats
        float mean1 = 0.f, inv1 = 0.f;
        {
            if (warp < 4) ln_stats(sm, XCOMB, lane, mean1, inv1);
            float4 acc = make_float4(0.f, 0.f, 0.f, 0.f);
#pragma unroll
            for (int k = 0; k < 8; ++k) {
                float xv = sm[XCOMB + warp * 8 + k];
                float4 w = w1r[k];
                acc.x = fmaf(xv, w.x, acc.x); acc.y = fmaf(xv, w.y, acc.y);
                acc.z = fmaf(xv, w.z, acc.z); acc.w = fmaf(xv, w.w, acc.w);
            }
            part4[warp * 32 + lane] = acc;
        }
        __syncthreads();                                              // B2
        if (tid < 128) {
            float s = red16(sm, tid);
            sm[XV1 + tid] = inv1 * (s - mean1 * sm[XC1 + tid]) + sm[XC2 + tid] + sm[XB1 + tid];
        }
        __syncthreads();                                              // B3

        // L2: inline relu(LN(v1)) -> matvec with w2r
        {
            float mean, inv;
            ln_stats(sm, XV1, lane, mean, inv);
            float4 acc = make_float4(0.f, 0.f, 0.f, 0.f);
#pragma unroll
            for (int k = 0; k < 8; ++k) {
                int idx = warp * 8 + k;
                float xv = fmaxf((sm[XV1 + idx] - mean) * inv * sm[XE1G + idx] + sm[XE1B + idx], 0.f);
                float4 w = w2r[k];
                acc.x = fmaf(xv, w.x, acc.x); acc.y = fmaf(xv, w.y, acc.y);
                acc.z = fmaf(xv, w.z, acc.z); acc.w = fmaf(xv, w.w, acc.w);
            }
            part4[warp * 32 + lane] = acc;
        }
        __syncthreads();                                              // B4
        if (tid < 128) sm[XV2 + tid] = red16(sm, tid) + sm[XB2 + tid];
        __syncthreads();                                              // B5

        // L3: inline relu(LN(v2)) -> matvec with SMEM W3
        {
            float mean, inv;
            ln_stats(sm, XV2, lane, mean, inv);
            float4 acc = make_float4(0.f, 0.f, 0.f, 0.f);
#pragma unroll
            for (int k = 0; k < 8; ++k) {
                int idx = warp * 8 + k;
                float xv = fmaxf((sm[XV2 + idx] - mean) * inv * sm[XE2G + idx] + sm[XE2B + idx], 0.f);
                float4 w = W34[k * 32];
                acc.x = fmaf(xv, w.x, acc.x); acc.y = fmaf(xv, w.y, acc.y);
                acc.z = fmaf(xv, w.z, acc.z); acc.w = fmaf(xv, w.w, acc.w);
            }
            part4[warp * 32 + lane] = acc;
        }
        __syncthreads();                                              // B6

        // P1: s reduce + keep state copy (XCOMB dead after L1) + push states
        if (tid < 128) {
            float v = red16(sm, tid) + sm[XB3 + tid];
            sm[XSOWN + tid] = v;
            sm[XCOMB + tid] = v;
            push_async(sm, xst, XMB + 0, rank, tid, v);
        }
        mbar_wait(sm, XMB + 0, par);                                  // E1

        // MP1: warp-local msg (lanes<8) + shfl, matvec with Wmsg (SMEM)
        {
            float msgv = 0.f;
            if (lane < 8) {
                int k = warp * 8 + lane;
#pragma unroll
                for (int jm = 0; jm < MM; ++jm)
                    msgv = fmaf(sm[XCG + jm], sm[xst + jm * 128 + k], msgv);
            }
            float4 acc = make_float4(0.f, 0.f, 0.f, 0.f);
#pragma unroll
            for (int k = 0; k < 8; ++k) {
                float xv = __shfl_sync(0xffffffffu, msgv, k);
                float4 w = Wm4[k * 32];
                acc.x = fmaf(xv, w.x, acc.x); acc.y = fmaf(xv, w.y, acc.y);
                acc.z = fmaf(xv, w.z, acc.z); acc.w = fmaf(xv, w.w, acc.w);
            }
            part4[warp * 32 + lane] = acc;
        }
        __syncthreads();                                              // B7

        // P2: y1 reduce + s update + push XSA
        if (tid < 128) {
            float y = red16(sm, tid);
            float ns = sm[XSOWN + tid] + fmaxf(y, 0.f);
            sm[XSOWN + tid] = ns;
            push_async(sm, XSA, XMB + 2, rank, tid, ns);
        }
        mbar_wait(sm, XMB + 2, par);                                  // E2

        // MP2 + park cur(t+1) into XCUR
        {
            if (tid < 128 && t < SL - 1) sm[XCUR + tid] = pref;
            float msgv = 0.f;
            if (lane < 8) {
                int k = warp * 8 + lane;
#pragma unroll
                for (int jm = 0; jm < MM; ++jm)
                    msgv = fmaf(sm[XCG + jm], sm[XSA + jm * 128 + k], msgv);
            }
            float4 acc = make_float4(0.f, 0.f, 0.f, 0.f);
#pragma unroll
            for (int k = 0; k < 8; ++k) {
                float xv = __shfl_sync(0xffffffffu, msgv, k);
                float4 w = Wm4[k * 32];
                acc.x = fmaf(xv, w.x, acc.x); acc.y = fmaf(xv, w.y, acc.y);
                acc.z = fmaf(xv, w.z, acc.z); acc.w = fmaf(xv, w.w, acc.w);
            }
            part4[warp * 32 + lane] = acc;
        }
        __syncthreads();                                              // B8

        // P3: y2 reduce + push CONTRIBUTION g_rank*state + 0.125*s_final
        if (tid < 128) {
            float y = red16(sm, tid);
            float sfin = sm[XSOWN + tid] + fmaxf(y, 0.f);
            float contrib = fmaf(sm[XG + rank], sm[XCOMB + tid], 0.125f * sfin);
            push_async(sm, XSB, XMB + 4, rank, tid, contrib);
        }
        mbar_wait(sm, XMB + 4, par);                                  // E3

        // agg = sum of contributions
        if (tid < 128) {
            float agg = 0.f;
#pragma unroll
            for (int m = 0; m < MM; ++m) agg += sm[XSB + m * 128 + tid];
            sm[XAGG + tid] = agg;
            if (rank == 0) g_out[(b * SL + t) * DD + tid] = agg;
        }
        __syncthreads();                                              // B9

        if (t < SL - 1) {
            // write-attention scores: warp w -> XATTW[w]
            {
                float p = 0.f;
#pragma unroll
                for (int c = 0; c < 4; ++c) {
                    int k = lane + 32 * c;
                    p = fmaf(sm[XAGG + k], sm[XMEM + warp * DD + k], p);
                }
                p = wsum(p);
                if (lane == 0) sm[XATTW + warp] = p * SCALE_D;
            }
            __syncthreads();                                          // B10

            // TAIL: mem update (warp n owns row n) + fused next-step read score
            {
                float vv = (lane < NM) ? sm[XATTW + lane] : -1e30f;
                float mx = wmaxf(vv);
                float e = (lane < NM) ? expf(vv - mx) : 0.f;
                float ss = wsum(e);
                float aval = e / ss;
                float wn = __shfl_sync(0xffffffffu, aval, warp);
                float p = 0.f;
#pragma unroll
                for (int c = 0; c < 4; ++c) {
                    int k = lane + 32 * c;
                    float nm = fmaf(wn, sm[XAGG + k], sm[XMEM + warp * DD + k]);
                    sm[XMEM + warp * DD + k] = nm;
                    p = fmaf(sm[XCUR + k], nm, p);
                }
                p = wsum(p);
                if (lane == 0) sm[nxatr + warp] = p * SCALE_D;
                if (tid >= 128 && tid < 136) sm[XG + tid - 128] = pref;
                else if (tid >= 136 && tid < 144) sm[XCR + tid - 136] = pref;
            }
            __syncthreads();                                          // B11
        }
    }
}

// ---------------- K4: QKV projections (split over blockIdx.y) ----------------
__global__ void qkv_kernel(const float* __restrict__ Wq, const float* __restrict__ Wk,
                           const float* __restrict__ Wv) {
    __shared__ float xs[32 * 128];
    int tid = threadIdx.x;
    int rowbase = blockIdx.x * 32;
    for (int idx = tid; idx < 4096; idx += 256) xs[idx] = g_out[rowbase * 128 + idx];
    __syncthreads();
    int rh = tid >> 7, jj = tid & 127;
    int w = blockIdx.y;
    const float* W = (w == 0) ? Wq : ((w == 1) ? Wk : Wv);
    float* O = (w == 0) ? g_q : ((w == 1) ? g_k : g_v);
    float acc[16];
#pragma unroll
    for (int r = 0; r < 16; ++r) acc[r] = 0.f;
    for (int k = 0; k < 128; ++k) {
        float wv = W[k * 128 + jj];
#pragma unroll
        for (int r = 0; r < 16; ++r) acc[r] = fmaf(xs[(rh * 16 + r) * 128 + k], wv, acc[r]);
    }
    int h = jj >> 5, dh = jj & 31;
#pragma unroll
    for (int r = 0; r < 16; ++r) {
        int row = rowbase + rh * 16 + r;
        int bb = row >> 9, s = row & 511;
        O[((bb * 4 + h) * SL + s) * 32 + dh] = acc[r];
    }
}

// ---------------- K5: sparse attention ----------------
__global__ void __launch_bounds__(256) attn_kernel() {
    extern __shared__ float ash[];
    float* kt = ash;              // 16384
    float* vt = ash + 16384;      // 16384
    float* cp = ash + 32768;      // 8192
    int tid = threadIdx.x, warp = tid >> 5, lane = tid & 31;
    int bh = blockIdx.x;
    const float* kb = g_k + bh * SL * 32;
    const float* vb = g_v + bh * SL * 32;
    for (int idx = tid; idx < SL * 32; idx += 256) {
        int n = idx >> 5, dh = idx & 31, sw = (dh + n) & 31;
        kt[n * 32 + sw] = kb[idx];
        vt[n * 32 + sw] = vb[idx];
    }
    __syncthreads();

    int qrow = blockIdx.y * 8 + warp;
    float qv = g_q[bh * SL * 32 + qrow * 32 + lane];
    float sc[16];
#pragma unroll
    for (int c = 0; c < 16; ++c) sc[c] = 0.f;
    for (int dh = 0; dh < 32; ++dh) {
        float qd = __shfl_sync(0xffffffffu, qv, dh);
#pragma unroll
        for (int c = 0; c < 16; ++c) {
            int n = c * 32 + lane;
            sc[c] = fmaf(qd, kt[n * 32 + ((dh + n) & 31)], sc[c]);
        }
    }
#pragma unroll
    for (int c = 0; c < 16; ++c) sc[c] *= SCALE_DH;

    unsigned eu[16];
#pragma unroll
    for (int c = 0; c < 16; ++c) {
        unsigned u = __float_as_uint(sc[c]);
        eu[c] = (u & 0x80000000u) ? ~u : (u | 0x80000000u);
    }
    unsigned thr = 0;
    for (int bit = 31; bit >= 0; --bit) {
        unsigned cand = thr | (1u << bit);
        int cnt = 0;
#pragma unroll
        for (int c = 0; c < 16; ++c) cnt += (eu[c] >= cand) ? 1 : 0;
        cnt = rsumi(cnt);
        if (cnt >= KK) thr = cand;
    }

    float mloc = -1e30f;
#pragma unroll
    for (int c = 0; c < 16; ++c) mloc = fmaxf(mloc, sc[c]);
    float mx = wmaxf(mloc);
    float ssum = 0.f;
#pragma unroll
    for (int c = 0; c < 16; ++c) ssum += (eu[c] >= thr) ? expf(sc[c] - mx) : 0.f;
    ssum = wsum(ssum);
    float inv = 1.f / ssum;

    float cx[32];
#pragma unroll
    for (int dh = 0; dh < 32; ++dh) cx[dh] = 0.f;
#pragma unroll 1
    for (int c = 0; c < 16; ++c) {
        float a = (eu[c] >= thr) ? expf(sc[c] - mx) * inv : 0.f;
        int n = c * 32 + lane;
#pragma unroll
        for (int dh = 0; dh < 32; ++dh)
            cx[dh] = fmaf(a, vt[n * 32 + ((dh + n) & 31)], cx[dh]);
    }

    float* cw = cp + warp * 1024;
#pragma unroll
    for (int dh = 0; dh < 32; ++dh) cw[lane * 32 + ((dh + lane) & 31)] = cx[dh];
    __syncwarp();
    float tot = 0.f;
#pragma unroll
    for (int src = 0; src < 32; ++src) tot += cw[src * 32 + ((lane + src) & 31)];
    int bb = bh >> 2, h = bh & 3;
    g_ctx[(bb * SL + qrow) * DD + h * 32 + lane] = tot;
}

// ---------------- K6: fused (ctx@Wo) then relu(.@Wd1+bd1) -> g_d1 ----------------
__global__ void gemm_out_kernel(const float* __restrict__ Wo,
                                const float* __restrict__ Wd1,
                                const float* __restrict__ bd1) {
    __shared__ float xs[32 * 128];
    __shared__ float ys[32 * 128];
    int tid = threadIdx.x;
    int rowbase = blockIdx.x * 32;
    for (int idx = tid; idx < 4096; idx += 256) xs[idx] = g_ctx[rowbase * 128 + idx];
    __syncthreads();
    int rh = tid >> 7, jj = tid & 127;
    float acc[16];
#pragma unroll
    for (int r = 0; r < 16; ++r) acc[r] = 0.f;
    for (int k = 0; k < 128; ++k) {
        float wv = Wo[k * 128 + jj];
#pragma unroll
        for (int r = 0; r < 16; ++r) acc[r] = fmaf(xs[(rh * 16 + r) * 128 + k], wv, acc[r]);
    }
#pragma unroll
    for (int r = 0; r < 16; ++r) ys[(rh * 16 + r) * 128 + jj] = acc[r];
    __syncthreads();
#pragma unroll
    for (int r = 0; r < 16; ++r) acc[r] = 0.f;
    for (int k = 0; k < 128; ++k) {
        float wv = Wd1[k * 128 + jj];
#pragma unroll
        for (int r = 0; r < 16; ++r) acc[r] = fmaf(ys[(rh * 16 + r) * 128 + k], wv, acc[r]);
    }
    float bb = bd1[jj];
#pragma unroll
    for (int r = 0; r < 16; ++r)
        g_d1[(rowbase + rh * 16 + r) * 128 + jj] = fmaxf(acc[r] + bb, 0.f);
}

// ---------------- K7: decoder [2048,128]@[128,32000] with f32x2 FMA ----------------
__global__ void __launch_bounds__(256) decoder_kernel(const float* __restrict__ Wd2,
                                                      const float* __restrict__ bd2,
                                                      float* __restrict__ out) {
    extern __shared__ float At[];   // 128*132 transposed A tile
    int tid = threadIdx.x;
    int rowbase = blockIdx.x * 128;
    for (int idx = tid; idx < 16384; idx += 256) {
        int r = idx >> 7, k = idx & 127;
        At[k * 132 + r] = g_d1[(rowbase + r) * 128 + k];
    }
    __syncthreads();
    int j = blockIdx.y * 64 + (tid & 63);
    int rq = tid >> 6;
    unsigned long long acc2[16];
#pragma unroll
    for (int i = 0; i < 16; ++i) acc2[i] = 0ull;
    const float* Bp = Wd2 + j;
    for (int k = 0; k < 128; ++k) {
        float w = Bp[(size_t)k * VOCAB];
        unsigned long long wp;
        asm("mov.b64 %0, {%1, %1};" : "=l"(wp) : "f"(w));
        const ulonglong2* a2 = reinterpret_cast<const ulonglong2*>(At + k * 132) + rq * 8;
#pragma unroll
        for (int rr = 0; rr < 8; ++rr) {
            ulonglong2 p = a2[rr];
            acc2[rr * 2]     = ffma2(p.x, wp, acc2[rr * 2]);
            acc2[rr * 2 + 1] = ffma2(p.y, wp, acc2[rr * 2 + 1]);
        }
    }
    float bb = bd2[j];
#pragma unroll
    for (int i = 0; i < 16; ++i) {
        float lo, hi;
        asm("mov.b64 {%0, %1}, %2;" : "=f"(lo), "=f"(hi) : "l"(acc2[i]));
        int row = rowbase + rq * 32 + i * 2;
        out[(size_t)row * VOCAB + j] = lo + bb;
        out[(size_t)(row + 1) * VOCAB + j] = hi + bb;
    }
}

// ---------------- launch ----------------
extern "C" void kernel_launch(void* const* d_in, const int* in_sizes, int n_in,
                              void* d_out, int out_size) {
    int off = (n_in > 30) ? 1 : 0;  // skip task_id if present
    const int*   seq  = (const int*)d_in[0];
    const float* emb  = (const float*)d_in[1 + off];
    const float* pos  = (const float*)d_in[2 + off];
    const float* Wr1  = (const float*)d_in[3 + off];
    const float* br1  = (const float*)d_in[4 + off];
    const float* Wr2  = (const float*)d_in[5 + off];
    const float* br2  = (const float*)d_in[6 + off];
    const float* ln_g = (const float*)d_in[7 + off];
    const float* ln_b = (const float*)d_in[8 + off];
    const float* eW1  = (const float*)d_in[9 + off];
    const float* eb1  = (const float*)d_in[10 + off];
    const float* e1g  = (const float*)d_in[11 + off];
    const float* e1b  = (const float*)d_in[12 + off];
    const float* eW2  = (const float*)d_in[13 + off];
    const float* eb2  = (const float*)d_in[14 + off];
    const float* e2g  = (const float*)d_in[15 + off];
    const float* e2b  = (const float*)d_in[16 + off];
    const float* eW3  = (const float*)d_in[17 + off];
    const float* eb3  = (const float*)d_in[18 + off];
    const float* mem0 = (const float*)d_in[19 + off];
    const float* Wmsg = (const float*)d_in[20 + off];
    const float* conn0= (const float*)d_in[21 + off];
    const float* Wq   = (const float*)d_in[22 + off];
    const float* Wk   = (const float*)d_in[23 + off];
    const float* Wv   = (const float*)d_in[24 + off];
    const float* Wo   = (const float*)d_in[25 + off];
    const float* Wd1  = (const float*)d_in[26 + off];
    const float* bd1  = (const float*)d_in[27 + off];
    const float* Wd2  = (const float*)d_in[28 + off];
    const float* bd2  = (const float*)d_in[29 + off];

    cudaFuncSetAttribute(conn_kernel, cudaFuncAttributeMaxDynamicSharedMemorySize, NB * SL * MM * 4);
    cudaFuncSetAttribute(scan_kernel, cudaFuncAttributeMaxDynamicSharedMemorySize, SCAN_SMEM_BYTES);
    cudaFuncSetAttribute(attn_kernel, cudaFuncAttributeMaxDynamicSharedMemorySize, 40960 * 4);
    cudaFuncSetAttribute(decoder_kernel, cudaFuncAttributeMaxDynamicSharedMemorySize, 128 * 132 * 4);

    gates_kernel<<<NB * SL / 8, 256>>>(seq, emb, pos, Wr1, br1, Wr2, br2);
    conn_kernel<<<1, 64, NB * SL * MM * 4>>>(conn0);
    scan_kernel<<<NB * MM, 512, SCAN_SMEM_BYTES>>>(mem0, Wmsg, ln_g, ln_b,
                                                   eW1, eb1, e1g, e1b,
                                                   eW2, eb2, e2g, e2b, eW3, eb3);
    qkv_kernel<<<dim3(NB * SL / 32, 3), 256>>>(Wq, Wk, Wv);
    attn_kernel<<<dim3(NB * 4, SL / 8), 256, 40960 * 4>>>();
    gemm_out_kernel<<<NB * SL / 32, 256>>>(Wo, Wd1, bd1);
    decoder_kernel<<<dim3(NB * SL / 128, VOCAB / 64), 256, 128 * 132 * 4>>>(Wd2, bd2, (float*)d_out);
}

// round 17
// speedup vs baseline: 1.2683x; 1.0101x over previous
#include <cuda_runtime.h>
#include <cooperative_groups.h>
#include <math.h>

namespace cg = cooperative_groups;

#define NB 4
#define SL 512
#define VOCAB 32000
#define DD 128
#define MM 8
#define NM 16
#define KK 153
#define LAMBDA 0.0025f
#define SCALE_D 0.08838834764831845f   /* 1/sqrt(128) */
#define SCALE_DH 0.17677669529663687f  /* 1/sqrt(32)  */

// ---------------- scratch ----------------
__device__ float g_x[NB*SL*DD];
__device__ float g_gates[NB*SL*MM];
__device__ float g_conn[SL*MM*MM];
__device__ float g_out[NB*SL*DD];
__device__ float g_q[NB*4*SL*32];
__device__ float g_k[NB*4*SL*32];
__device__ float g_v[NB*4*SL*32];
__device__ float g_ctx[NB*SL*DD];
__device__ float g_d1[NB*SL*DD];

// ---------------- helpers ----------------
__device__ __forceinline__ float wsum(float v) {
#pragma unroll
    for (int o = 16; o; o >>= 1) v += __shfl_xor_sync(0xffffffffu, v, o);
    return v;
}
__device__ __forceinline__ float wmaxf(float v) {
#pragma unroll
    for (int o = 16; o; o >>= 1) v = fmaxf(v, __shfl_xor_sync(0xffffffffu, v, o));
    return v;
}
__device__ __forceinline__ int rsumi(int v) {
    int r;
    asm volatile("redux.sync.add.u32 %0, %1, 0xffffffff;" : "=r"(r) : "r"(v));
    return r;
}
__device__ __forceinline__ unsigned long long ffma2(unsigned long long a,
                                                    unsigned long long b,
                                                    unsigned long long c) {
    unsigned long long d;
    asm("fma.rn.f32x2 %0, %1, %2, %3;" : "=l"(d) : "l"(a), "l"(b), "l"(c));
    return d;
}
__device__ __forceinline__ unsigned smaddr(const void* p) {
    unsigned a;
    asm("{ .reg .u64 t; cvta.to.shared.u64 t, %1; cvt.u32.u64 %0, t; }" : "=r"(a) : "l"(p));
    return a;
}

// ---------------- K1: embed + router gates (fused) ----------------
__global__ void gates_kernel(const int* __restrict__ seq,
                             const float* __restrict__ emb,
                             const float* __restrict__ pos,
                             const float* __restrict__ Wr1, const float* __restrict__ br1,
                             const float* __restrict__ Wr2, const float* __restrict__ br2) {
    __shared__ float xs[8][DD];
    int warp = threadIdx.x >> 5, lane = threadIdx.x & 31;
    int row = blockIdx.x * 8 + warp;
    int s = row & (SL - 1);
    int tok = seq[row];
#pragma unroll
    for (int c = 0; c < 4; ++c) {
        int k = lane + 32 * c;
        float xv = emb[tok * DD + k] + pos[s * DD + k];
        xs[warp][k] = xv;
        g_x[row * DD + k] = xv;
    }
    __syncwarp();

    float acc[4] = {0.f, 0.f, 0.f, 0.f};
    for (int k = 0; k < DD; ++k) {
        float a = xs[warp][k];
#pragma unroll
        for (int c = 0; c < 4; ++c) acc[c] = fmaf(a, Wr1[k * DD + lane + 32 * c], acc[c]);
    }
    float t1[4];
#pragma unroll
    for (int c = 0; c < 4; ++c) t1[c] = fmaxf(acc[c] + br1[lane + 32 * c], 0.f);

    float y[MM];
#pragma unroll
    for (int m = 0; m < MM; ++m) {
        float p = 0.f;
#pragma unroll
        for (int c = 0; c < 4; ++c) p = fmaf(t1[c], Wr2[(lane + 32 * c) * MM + m], p);
        p = wsum(p);
        y[m] = p + br2[m];
    }
    float mx = y[0];
#pragma unroll
    for (int m = 1; m < MM; ++m) mx = fmaxf(mx, y[m]);
    float ssum = 0.f;
#pragma unroll
    for (int m = 0; m < MM; ++m) { y[m] = expf(y[m] - mx); ssum += y[m]; }
    if (lane == 0) {
        float inv = 1.f / ssum;
#pragma unroll
        for (int m = 0; m < MM; ++m) g_gates[row * MM + m] = y[m] * inv;
    }
}

// ---------------- K2: Hebbian conn prefix ----------------
__global__ void conn_kernel(const float* __restrict__ conn0) {
    extern __shared__ float gs[];   // NB*SL*MM floats
    int tid = threadIdx.x;          // 64 threads
    for (int i = tid; i < NB * SL * MM; i += 64) gs[i] = g_gates[i];
    __syncthreads();
    int i = tid >> 3, j = tid & 7;
    float c = conn0[tid];
    for (int t = 0; t < SL; ++t) {
        g_conn[t * 64 + tid] = c;
        float v = 0.f;
#pragma unroll
        for (int b = 0; b < NB; ++b)
            v += gs[(b * SL + t) * MM + i] * gs[(b * SL + t) * MM + j];
        c += LAMBDA * v;
    }
}

// ---------------- K3: scan ----------------
// SMEM float offsets
#define XW3   0        // 16384 (own module eW3)
#define XMEM  16384    // 2048
#define XB1   18432
#define XE1G  18560
#define XE1B  18688
#define XB2   18816
#define XE2G  18944
#define XE2B  19072
#define XB3   19200
#define XLNG  19328
#define XLNB  19456
#define XCUR  19584
#define XCOMB 19712
#define XV1   19840
#define XV2   19968
#define XAGG  20096
#define XSOWN 20224
#define XST0  20352    // 1024 (states, parity 0)
#define XST1  21376    // 1024 (states, parity 1)
#define XSA   22400    // 1024
#define XSB   23424    // 1024 (contributions)
#define XPART 24448    // 2048
#define XATR0 26496    // 16 (read scores, parity 0)
#define XATR1 26512    // 16 (read scores, parity 1)
#define XATTW 26528    // 16 (write-attention scores)
#define XG    26544    // 8
#define XCR   26552    // 8
#define XCG   26560    // 8
#define XMB   26568    // 8 (3 mbarriers: +0,+2,+4)
#define XWM   26576    // 16384 (Wmsg)
#define XC1   42960    // 128 (sum_j ln_g[j]*W1[j][o])
#define XC2   43088    // 128 (sum_j ln_b[j]*W1[j][o])
#define XTOT  43216
#define SCAN_SMEM_BYTES (XTOT * 4)
#define EXCH_BYTES 4096u   /* 8 ranks x 128 floats */

__device__ __forceinline__ float red16(const float* sm, int tid) {  // tid < 128
    float v = 0.f;
#pragma unroll
    for (int q = 0; q < 16; ++q) v += sm[XPART + q * 128 + tid];
    return v;
}

// warp-replicated LN stats of a 128-vector at sm[off] -> mean, inv
__device__ __forceinline__ void ln_stats(const float* sm, int off, int lane,
                                         float& mean, float& inv) {
    float a0 = sm[off + lane], a1 = sm[off + 32 + lane];
    float a2 = sm[off + 64 + lane], a3 = sm[off + 96 + lane];
    float s1 = wsum(a0 + a1 + a2 + a3);
    float s2 = wsum(fmaf(a0, a0, fmaf(a1, a1, fmaf(a2, a2, a3 * a3))));
    mean = s1 * (1.f / 128.f);
    float var = s2 * (1.f / 128.f) - mean * mean;
    inv = rsqrtf(var + 1e-5f);
}

// push value v into slot (rank*128 + d) of buffer `dstoff` in ALL 8 cluster CTAs
__device__ __forceinline__ void push_async(float* sm, int dstoff, int mboff,
                                           int rank, int d, float v) {
    unsigned dst0 = smaddr(sm + dstoff + rank * 128 + d);
    unsigned mb0 = smaddr(sm + mboff);
    unsigned vi = __float_as_uint(v);
#pragma unroll
    for (int r = 0; r < MM; ++r) {
        unsigned dst, mb;
        asm("mapa.shared::cluster.u32 %0, %1, %2;" : "=r"(dst) : "r"(dst0), "r"(r));
        asm("mapa.shared::cluster.u32 %0, %1, %2;" : "=r"(mb) : "r"(mb0), "r"(r));
        asm volatile("st.async.shared::cluster.mbarrier::complete_tx::bytes.b32 [%0], %1, [%2];"
                     :: "r"(dst), "r"(vi), "r"(mb) : "memory");
    }
}

__device__ __forceinline__ void mbar_wait(float* sm, int mboff, unsigned parity) {
    unsigned mb = smaddr(sm + mboff);
    asm volatile(
        "{\n\t.reg .pred P;\n"
        "W%=:\n\t"
        "mbarrier.try_wait.parity.acquire.cluster.shared::cta.b64 P, [%0], %1, 0x989680;\n\t"
        "@P bra.uni D%=;\n\t"
        "bra.uni W%=;\n"
        "D%=:\n\t}"
        :: "r"(mb), "r"(parity) : "memory");
}

__global__ void __launch_bounds__(512, 1) __cluster_dims__(MM, 1, 1) scan_kernel(
    const float* __restrict__ mem0, const float* __restrict__ Wmsg,
    const float* __restrict__ ln_g, const float* __restrict__ ln_b,
    const float* __restrict__ eW1, const float* __restrict__ eb1,
    const float* __restrict__ e1g, const float* __restrict__ e1b,
    const float* __restrict__ eW2, const float* __restrict__ eb2,
    const float* __restrict__ e2g, const float* __restrict__ e2b,
    const float* __restrict__ eW3, const float* __restrict__ eb3) {
    extern __shared__ float sm[];
    cg::cluster_group cluster = cg::this_cluster();
    int tid = threadIdx.x;
    int rank = (int)cluster.block_rank();        // module index
    int b = blockIdx.x >> 3;                     // batch index
    int warp = tid >> 5, lane = tid & 31;        // warp == k-group (16)

    // register-resident W1, W2: thread (kq=warp, jq=lane) holds its 8 weight quads
    float4 w1r[8], w2r[8];
    {
        const float4* W1g = reinterpret_cast<const float4*>(eW1 + (size_t)rank * 16384);
        const float4* W2g = reinterpret_cast<const float4*>(eW2 + (size_t)rank * 16384);
        int base = (warp * 8) * 32 + lane;
#pragma unroll
        for (int k = 0; k < 8; ++k) {
            w1r[k] = W1g[base + k * 32];
            w2r[k] = W2g[base + k * 32];
        }
        const float* w3 = eW3 + (size_t)rank * 16384;
        for (int i = tid; i < 16384; i += 512) {
            sm[XW3 + i] = w3[i];
            sm[XWM + i] = Wmsg[i];
        }
        for (int i = tid; i < 2048; i += 512) sm[XMEM + i] = mem0[i];
        if (tid < 128) {
            sm[XB1 + tid]  = eb1[rank * 128 + tid];
            sm[XE1G + tid] = e1g[rank * 128 + tid];
            sm[XE1B + tid] = e1b[rank * 128 + tid];
            sm[XB2 + tid]  = eb2[rank * 128 + tid];
            sm[XE2G + tid] = e2g[rank * 128 + tid];
            sm[XE2B + tid] = e2b[rank * 128 + tid];
            sm[XB3 + tid]  = eb3[rank * 128 + tid];
            sm[XLNG + tid] = ln_g[tid];
            sm[XLNB + tid] = ln_b[tid];
        }
        // t=0 step inputs
        if (tid < 128) sm[XCUR + tid] = g_x[(b * SL) * DD + tid];
        else if (tid < 136) sm[XG + tid - 128] = g_gates[(b * SL) * MM + (tid - 128)];
        else if (tid < 144) sm[XCR + tid - 136] = g_conn[rank * 8 + (tid - 136)];
        if (tid == 0) {
#pragma unroll
            for (int q = 0; q < 3; ++q) {
                unsigned mb = smaddr(sm + XMB + 2 * q);
                asm volatile("mbarrier.init.shared.b64 [%0], %1;" :: "r"(mb), "r"(1u) : "memory");
            }
        }
    }
    cluster.sync();   // all SMEM + mbarriers ready cluster-wide

    float4* part4 = reinterpret_cast<float4*>(sm + XPART);
    float4* partB4 = reinterpret_cast<float4*>(sm + XSA);  // scratch during prologue
    const float4* Wm4 = reinterpret_cast<const float4*>(sm + XWM) + (warp * 8) * 32 + lane;
    const float4* W34 = reinterpret_cast<const float4*>(sm + XW3) + (warp * 8) * 32 + lane;

    // prologue 1: fold ln_g into w1r; build c1/c2 partials
    {
        float4 a2c = make_float4(0.f, 0.f, 0.f, 0.f);  // sum W1*ln_b
        float4 a1c = make_float4(0.f, 0.f, 0.f, 0.f);  // sum (W1*ln_g)
#pragma unroll
        for (int k = 0; k < 8; ++k) {
            int idx = warp * 8 + k;
            float lb = sm[XLNB + idx], lg = sm[XLNG + idx];
            a2c.x = fmaf(w1r[k].x, lb, a2c.x); a2c.y = fmaf(w1r[k].y, lb, a2c.y);
            a2c.z = fmaf(w1r[k].z, lb, a2c.z); a2c.w = fmaf(w1r[k].w, lb, a2c.w);
            w1r[k].x *= lg; w1r[k].y *= lg; w1r[k].z *= lg; w1r[k].w *= lg;
            a1c.x += w1r[k].x; a1c.y += w1r[k].y; a1c.z += w1r[k].z; a1c.w += w1r[k].w;
        }
        part4[warp * 32 + lane] = a2c;
        partB4[warp * 32 + lane] = a1c;
    }
    __syncthreads();
    if (tid < 128) {
        float s2c = 0.f, s1c = 0.f;
#pragma unroll
        for (int q = 0; q < 16; ++q) {
            s2c += sm[XPART + q * 128 + tid];
            s1c += sm[XSA + q * 128 + tid];
        }
        sm[XC2 + tid] = s2c;
        sm[XC1 + tid] = s1c;
    }
    // prologue 2: read-attention scores for t=0 (warp w -> slot w)
    {
        float pp = 0.f;
#pragma unroll
        for (int c = 0; c < 4; ++c) {
            int k = lane + 32 * c;
            pp = fmaf(sm[XCUR + k], sm[XMEM + warp * DD + k], pp);
        }
        pp = wsum(pp);
        if (lane == 0) sm[XATR0 + warp] = pp * SCALE_D;
    }
    __syncthreads();

    for (int t = 0; t < SL; ++t) {
        int xst = (t & 1) ? XST1 : XST0;
        int xatr = (t & 1) ? XATR1 : XATR0;
        int nxatr = (t & 1) ? XATR0 : XATR1;
        unsigned par = (unsigned)(t & 1);
        if (tid == 0) {
#pragma unroll
            for (int q = 0; q < 3; ++q) {
                unsigned mb = smaddr(sm + XMB + 2 * q);
                asm volatile("mbarrier.arrive.expect_tx.shared.b64 _, [%0], %1;"
                             :: "r"(mb), "r"(EXCH_BYTES) : "memory");
            }
        } else if (tid >= 32 && tid < 40) sm[XCG + tid - 32] = sm[XCR + tid - 32] * sm[XG + tid - 32];
        // prefetch t+1 inputs into regs
        float pref = 0.f;
        if (t < SL - 1) {
            if (tid < 128) pref = g_x[(b * SL + t + 1) * DD + tid];
            else if (tid < 136) pref = g_gates[(b * SL + t + 1) * MM + (tid - 128)];
            else if (tid < 144) pref = g_conn[(t + 1) * 64 + rank * 8 + (tid - 136)];
        }

        // A: comb = cur + retrieved (softmax over precomputed scores), warps 0-3
        if (tid < 128) {
            float vv = (lane < NM) ? sm[xatr + lane] : -1e30f;
            float mx = wmaxf(vv);
            float e = (lane < NM) ? expf(vv - mx) : 0.f;
            float ss = wsum(e);
            float aval = e / ss;
            float r = 0.f;
#pragma unroll
            for (int n = 0; n < NM; ++n) {
                float an = __shfl_sync(0xffffffffu, aval, n);
                r = fmaf(an, sm[XMEM + n * DD + tid], r);
            }
            sm[XCOMB + tid] = sm[XCUR + tid] + r;
        }
        __syncthreads();                                              // B1

        // L1: matvec on RAW comb with ln_g-folded w1r; warps 0-3 compute stats
        float mean1 = 0.f, inv1 = 0.f;
        {
            if (warp < 4) ln_stats(sm, XCOMB, lane, mean1, inv1);
            float4 acc = make_float4(0.f, 0.f, 0.f, 0.f);
#pragma unroll
            for (int k = 0; k < 8; ++k) {
                float xv = sm[XCOMB + warp * 8 + k];
                float4 w = w1r[k];
                acc.x = fmaf(xv, w.x, acc.x); acc.y = fmaf(xv, w.y, acc.y);
                acc.z = fmaf(xv, w.z, acc.z); acc.w = fmaf(xv, w.w, acc.w);
            }
            part4[warp * 32 + lane] = acc;
        }
        __syncthreads();                                              // B2
        if (tid < 128) {
            float s = red16(sm, tid);
            sm[XV1 + tid] = inv1 * (s - mean1 * sm[XC1 + tid]) + sm[XC2 + tid] + sm[XB1 + tid];
        }
        __syncthreads();                                              // B3

        // L2: inline relu(LN(v1)) -> matvec with w2r
        {
            float mean, inv;
            ln_stats(sm, XV1, lane, mean, inv);
            float4 acc = make_float4(0.f, 0.f, 0.f, 0.f);
#pragma unroll
            for (int k = 0; k < 8; ++k) {
                int idx = warp * 8 + k;
                float xv = fmaxf((sm[XV1 + idx] - mean) * inv * sm[XE1G + idx] + sm[XE1B + idx], 0.f);
                float4 w = w2r[k];
                acc.x = fmaf(xv, w.x, acc.x); acc.y = fmaf(xv, w.y, acc.y);
                acc.z = fmaf(xv, w.z, acc.z); acc.w = fmaf(xv, w.w, acc.w);
            }
            part4[warp * 32 + lane] = acc;
        }
        __syncthreads();                                              // B4
        if (tid < 128) sm[XV2 + tid] = red16(sm, tid) + sm[XB2 + tid];
        __syncthreads();                                              // B5

        // L3: inline relu(LN(v2)) -> matvec with SMEM W3
        {
            float mean, inv;
            ln_stats(sm, XV2, lane, mean, inv);
            float4 acc = make_float4(0.f, 0.f, 0.f, 0.f);
#pragma unroll
            for (int k = 0; k < 8; ++k) {
                int idx = warp * 8 + k;
                float xv = fmaxf((sm[XV2 + idx] - mean) * inv * sm[XE2G + idx] + sm[XE2B + idx], 0.f);
                float4 w = W34[k * 32];
                acc.x = fmaf(xv, w.x, acc.x); acc.y = fmaf(xv, w.y, acc.y);
                acc.z = fmaf(xv, w.z, acc.z); acc.w = fmaf(xv, w.w, acc.w);
            }
            part4[warp * 32 + lane] = acc;
        }
        __syncthreads();                                              // B6

        // P1: s reduce + keep state copy (XCOMB dead after L1) + push states
        if (tid < 128) {
            float v = red16(sm, tid) + sm[XB3 + tid];
            sm[XSOWN + tid] = v;
            sm[XCOMB + tid] = v;
            push_async(sm, xst, XMB + 0, rank, tid, v);
        }
        mbar_wait(sm, XMB + 0, par);                                  // E1

        // MP1: warp-local msg (lanes<8) + shfl, matvec with Wmsg (SMEM)
        {
            float msgv = 0.f;
            if (lane < 8) {
                int k = warp * 8 + lane;
#pragma unroll
                for (int jm = 0; jm < MM; ++jm)
                    msgv = fmaf(sm[XCG + jm], sm[xst + jm * 128 + k], msgv);
            }
            float4 acc = make_float4(0.f, 0.f, 0.f, 0.f);
#pragma unroll
            for (int k = 0; k < 8; ++k) {
                float xv = __shfl_sync(0xffffffffu, msgv, k);
                float4 w = Wm4[k * 32];
                acc.x = fmaf(xv, w.x, acc.x); acc.y = fmaf(xv, w.y, acc.y);
                acc.z = fmaf(xv, w.z, acc.z); acc.w = fmaf(xv, w.w, acc.w);
            }
            part4[warp * 32 + lane] = acc;
        }
        __syncthreads();                                              // B7

        // P2: y1 reduce + s update + push XSA
        if (tid < 128) {
            float y = red16(sm, tid);
            float ns = sm[XSOWN + tid] + fmaxf(y, 0.f);
            sm[XSOWN + tid] = ns;
            push_async(sm, XSA, XMB + 2, rank, tid, ns);
        }
        mbar_wait(sm, XMB + 2, par);                                  // E2

        // MP2 + park cur(t+1) into XCUR
        {
            if (tid < 128 && t < SL - 1) sm[XCUR + tid] = pref;
            float msgv = 0.f;
            if (lane < 8) {
                int k = warp * 8 + lane;
#pragma unroll
                for (int jm = 0; jm < MM; ++jm)
                    msgv = fmaf(sm[XCG + jm], sm[XSA + jm * 128 + k], msgv);
            }
            float4 acc = make_float4(0.f, 0.f, 0.f, 0.f);
#pragma unroll
            for (int k = 0; k < 8; ++k) {
                float xv = __shfl_sync(0xffffffffu, msgv, k);
                float4 w = Wm4[k * 32];
                acc.x = fmaf(xv, w.x, acc.x); acc.y = fmaf(xv, w.y, acc.y);
                acc.z = fmaf(xv, w.z, acc.z); acc.w = fmaf(xv, w.w, acc.w);
            }
            part4[warp * 32 + lane] = acc;
        }
        __syncthreads();                                              // B8

        // P3: y2 reduce + push CONTRIBUTION g_rank*state + 0.125*s_final
        if (tid < 128) {
            float y = red16(sm, tid);
            float sfin = sm[XSOWN + tid] + fmaxf(y, 0.f);
            float contrib = fmaf(sm[XG + rank], sm[XCOMB + tid], 0.125f * sfin);
            push_async(sm, XSB, XMB + 4, rank, tid, contrib);
        }
        mbar_wait(sm, XMB + 4, par);                                  // E3

        // agg = sum of contributions
        if (tid < 128) {
            float agg = 0.f;
#pragma unroll
            for (int m = 0; m < MM; ++m) agg += sm[XSB + m * 128 + tid];
            sm[XAGG + tid] = agg;
            if (rank == 0) g_out[(b * SL + t) * DD + tid] = agg;
        }
        __syncthreads();                                              // B9

        if (t < SL - 1) {
            // write-attention scores: warp w -> XATTW[w]
            {
                float p = 0.f;
#pragma unroll
                for (int c = 0; c < 4; ++c) {
                    int k = lane + 32 * c;
                    p = fmaf(sm[XAGG + k], sm[XMEM + warp * DD + k], p);
                }
                p = wsum(p);
                if (lane == 0) sm[XATTW + warp] = p * SCALE_D;
            }
            __syncthreads();                                          // B10

            // TAIL: mem update (warp n owns row n) + fused next-step read score
            {
                float vv = (lane < NM) ? sm[XATTW + lane] : -1e30f;
                float mx = wmaxf(vv);
                float e = (lane < NM) ? expf(vv - mx) : 0.f;
                float ss = wsum(e);
                float aval = e / ss;
                float wn = __shfl_sync(0xffffffffu, aval, warp);
                float p = 0.f;
#pragma unroll
                for (int c = 0; c < 4; ++c) {
                    int k = lane + 32 * c;
                    float nm = fmaf(wn, sm[XAGG + k], sm[XMEM + warp * DD + k]);
                    sm[XMEM + warp * DD + k] = nm;
                    p = fmaf(sm[XCUR + k], nm, p);
                }
                p = wsum(p);
                if (lane == 0) sm[nxatr + warp] = p * SCALE_D;
                if (tid >= 128 && tid < 136) sm[XG + tid - 128] = pref;
                else if (tid >= 136 && tid < 144) sm[XCR + tid - 136] = pref;
            }
            __syncthreads();                                          // B11
        }
    }
}

// ---------------- K4: QKV projections (16 rows/block, split over blockIdx.y) ----------------
__global__ void qkv_kernel(const float* __restrict__ Wq, const float* __restrict__ Wk,
                           const float* __restrict__ Wv) {
    __shared__ float xs[16 * 128];
    int tid = threadIdx.x;
    int rowbase = blockIdx.x * 16;
    for (int idx = tid; idx < 2048; idx += 256) xs[idx] = g_out[rowbase * 128 + idx];
    __syncthreads();
    int rh = tid >> 7, jj = tid & 127;
    int w = blockIdx.y;
    const float* W = (w == 0) ? Wq : ((w == 1) ? Wk : Wv);
    float* O = (w == 0) ? g_q : ((w == 1) ? g_k : g_v);
    float acc[8];
#pragma unroll
    for (int r = 0; r < 8; ++r) acc[r] = 0.f;
    for (int k = 0; k < 128; ++k) {
        float wv = W[k * 128 + jj];
#pragma unroll
        for (int r = 0; r < 8; ++r) acc[r] = fmaf(xs[(rh * 8 + r) * 128 + k], wv, acc[r]);
    }
    int h = jj >> 5, dh = jj & 31;
#pragma unroll
    for (int r = 0; r < 8; ++r) {
        int row = rowbase + rh * 8 + r;
        int bb = row >> 9, s = row & 511;
        O[((bb * 4 + h) * SL + s) * 32 + dh] = acc[r];
    }
}

// ---------------- K5: sparse attention ----------------
__global__ void __launch_bounds__(256) attn_kernel() {
    extern __shared__ float ash[];
    float* kt = ash;              // 16384
    float* vt = ash + 16384;      // 16384
    float* cp = ash + 32768;      // 8192
    int tid = threadIdx.x, warp = tid >> 5, lane = tid & 31;
    int bh = blockIdx.x;
    const float* kb = g_k + bh * SL * 32;
    const float* vb = g_v + bh * SL * 32;
    for (int idx = tid; idx < SL * 32; idx += 256) {
        int n = idx >> 5, dh = idx & 31, sw = (dh + n) & 31;
        kt[n * 32 + sw] = kb[idx];
        vt[n * 32 + sw] = vb[idx];
    }
    __syncthreads();

    int qrow = blockIdx.y * 8 + warp;
    float qv = g_q[bh * SL * 32 + qrow * 32 + lane];
    float sc[16];
#pragma unroll
    for (int c = 0; c < 16; ++c) sc[c] = 0.f;
    for (int dh = 0; dh < 32; ++dh) {
        float qd = __shfl_sync(0xffffffffu, qv, dh);
#pragma unroll
        for (int c = 0; c < 16; ++c) {
            int n = c * 32 + lane;
            sc[c] = fmaf(qd, kt[n * 32 + ((dh + n) & 31)], sc[c]);
        }
    }
#pragma unroll
    for (int c = 0; c < 16; ++c) sc[c] *= SCALE_DH;

    unsigned eu[16];
#pragma unroll
    for (int c = 0; c < 16; ++c) {
        unsigned u = __float_as_uint(sc[c]);
        eu[c] = (u & 0x80000000u) ? ~u : (u | 0x80000000u);
    }
    unsigned thr = 0;
    for (int bit = 31; bit >= 0; --bit) {
        unsigned cand = thr | (1u << bit);
        int cnt = 0;
#pragma unroll
        for (int c = 0; c < 16; ++c) cnt += (eu[c] >= cand) ? 1 : 0;
        cnt = rsumi(cnt);
        if (cnt >= KK) thr = cand;
    }

    float mloc = -1e30f;
#pragma unroll
    for (int c = 0; c < 16; ++c) mloc = fmaxf(mloc, sc[c]);
    float mx = wmaxf(mloc);
    float ssum = 0.f;
#pragma unroll
    for (int c = 0; c < 16; ++c) ssum += (eu[c] >= thr) ? expf(sc[c] - mx) : 0.f;
    ssum = wsum(ssum);
    float inv = 1.f / ssum;

    float cx[32];
#pragma unroll
    for (int dh = 0; dh < 32; ++dh) cx[dh] = 0.f;
#pragma unroll 1
    for (int c = 0; c < 16; ++c) {
        float a = (eu[c] >= thr) ? expf(sc[c] - mx) * inv : 0.f;
        int n = c * 32 + lane;
#pragma unroll
        for (int dh = 0; dh < 32; ++dh)
            cx[dh] = fmaf(a, vt[n * 32 + ((dh + n) & 31)], cx[dh]);
    }

    float* cw = cp + warp * 1024;
#pragma unroll
    for (int dh = 0; dh < 32; ++dh) cw[lane * 32 + ((dh + lane) & 31)] = cx[dh];
    __syncwarp();
    float tot = 0.f;
#pragma unroll
    for (int src = 0; src < 32; ++src) tot += cw[src * 32 + ((lane + src) & 31)];
    int bb = bh >> 2, h = bh & 3;
    g_ctx[(bb * SL + qrow) * DD + h * 32 + lane] = tot;
}

// ---------------- K6: fused (ctx@Wo) then relu(.@Wd1+bd1) -> g_d1 (16 rows/block) ----------------
__global__ void gemm_out_kernel(const float* __restrict__ Wo,
                                const float* __restrict__ Wd1,
                                const float* __restrict__ bd1) {
    __shared__ float xs[16 * 128];
    __shared__ float ys[16 * 128];
    int tid = threadIdx.x;
    int rowbase = blockIdx.x * 16;
    for (int idx = tid; idx < 2048; idx += 256) xs[idx] = g_ctx[rowbase * 128 + idx];
    __syncthreads();
    int rh = tid >> 7, jj = tid & 127;
    float acc[8];
#pragma unroll
    for (int r = 0; r < 8; ++r) acc[r] = 0.f;
    for (int k = 0; k < 128; ++k) {
        float wv = Wo[k * 128 + jj];
#pragma unroll
        for (int r = 0; r < 8; ++r) acc[r] = fmaf(xs[(rh * 8 + r) * 128 + k], wv, acc[r]);
    }
#pragma unroll
    for (int r = 0; r < 8; ++r) ys[(rh * 8 + r) * 128 + jj] = acc[r];
    __syncthreads();
#pragma unroll
    for (int r = 0; r < 8; ++r) acc[r] = 0.f;
    for (int k = 0; k < 128; ++k) {
        float wv = Wd1[k * 128 + jj];
#pragma unroll
        for (int r = 0; r < 8; ++r) acc[r] = fmaf(ys[(rh * 8 + r) * 128 + k], wv, acc[r]);
    }
    float bb = bd1[jj];
#pragma unroll
    for (int r = 0; r < 8; ++r)
        g_d1[(rowbase + rh * 8 + r) * 128 + jj] = fmaxf(acc[r] + bb, 0.f);
}

// ---------------- K7: decoder [2048,128]@[128,32000] with f32x2 FMA ----------------
__global__ void __launch_bounds__(256) decoder_kernel(const float* __restrict__ Wd2,
                                                      const float* __restrict__ bd2,
                                                      float* __restrict__ out) {
    extern __shared__ float At[];   // 128*132 transposed A tile
    int tid = threadIdx.x;
    int rowbase = blockIdx.x * 128;
    for (int idx = tid; idx < 16384; idx += 256) {
        int r = idx >> 7, k = idx & 127;
        At[k * 132 + r] = g_d1[(rowbase + r) * 128 + k];
    }
    __syncthreads();
    int j = blockIdx.y * 64 + (tid & 63);
    int rq = tid >> 6;
    unsigned long long acc2[16];
#pragma unroll
    for (int i = 0; i < 16; ++i) acc2[i] = 0ull;
    const float* Bp = Wd2 + j;
    for (int k = 0; k < 128; ++k) {
        float w = Bp[(size_t)k * VOCAB];
        unsigned long long wp;
        asm("mov.b64 %0, {%1, %1};" : "=l"(wp) : "f"(w));
        const ulonglong2* a2 = reinterpret_cast<const ulonglong2*>(At + k * 132) + rq * 8;
#pragma unroll
        for (int rr = 0; rr < 8; ++rr) {
            ulonglong2 p = a2[rr];
            acc2[rr * 2]     = ffma2(p.x, wp, acc2[rr * 2]);
            acc2[rr * 2 + 1] = ffma2(p.y, wp, acc2[rr * 2 + 1]);
        }
    }
    float bb = bd2[j];
#pragma unroll
    for (int i = 0; i < 16; ++i) {
        float lo, hi;
        asm("mov.b64 {%0, %1}, %2;" : "=f"(lo), "=f"(hi) : "l"(acc2[i]));
        int row = rowbase + rq * 32 + i * 2;
        out[(size_t)row * VOCAB + j] = lo + bb;
        out[(size_t)(row + 1) * VOCAB + j] = hi + bb;
    }
}

// ---------------- launch ----------------
extern "C" void kernel_launch(void* const* d_in, const int* in_sizes, int n_in,
                              void* d_out, int out_size) {
    int off = (n_in > 30) ? 1 : 0;  // skip task_id if present
    const int*   seq  = (const int*)d_in[0];
    const float* emb  = (const float*)d_in[1 + off];
    const float* pos  = (const float*)d_in[2 + off];
    const float* Wr1  = (const float*)d_in[3 + off];
    const float* br1  = (const float*)d_in[4 + off];
    const float* Wr2  = (const float*)d_in[5 + off];
    const float* br2  = (const float*)d_in[6 + off];
    const float* ln_g = (const float*)d_in[7 + off];
    const float* ln_b = (const float*)d_in[8 + off];
    const float* eW1  = (const float*)d_in[9 + off];
    const float* eb1  = (const float*)d_in[10 + off];
    const float* e1g  = (const float*)d_in[11 + off];
    const float* e1b  = (const float*)d_in[12 + off];
    const float* eW2  = (const float*)d_in[13 + off];
    const float* eb2  = (const float*)d_in[14 + off];
    const float* e2g  = (const float*)d_in[15 + off];
    const float* e2b  = (const float*)d_in[16 + off];
    const float* eW3  = (const float*)d_in[17 + off];
    const float* eb3  = (const float*)d_in[18 + off];
    const float* mem0 = (const float*)d_in[19 + off];
    const float* Wmsg = (const float*)d_in[20 + off];
    const float* conn0= (const float*)d_in[21 + off];
    const float* Wq   = (const float*)d_in[22 + off];
    const float* Wk   = (const float*)d_in[23 + off];
    const float* Wv   = (const float*)d_in[24 + off];
    const float* Wo   = (const float*)d_in[25 + off];
    const float* Wd1  = (const float*)d_in[26 + off];
    const float* bd1  = (const float*)d_in[27 + off];
    const float* Wd2  = (const float*)d_in[28 + off];
    const float* bd2  = (const float*)d_in[29 + off];

    cudaFuncSetAttribute(conn_kernel, cudaFuncAttributeMaxDynamicSharedMemorySize, NB * SL * MM * 4);
    cudaFuncSetAttribute(scan_kernel, cudaFuncAttributeMaxDynamicSharedMemorySize, SCAN_SMEM_BYTES);
    cudaFuncSetAttribute(attn_kernel, cudaFuncAttributeMaxDynamicSharedMemorySize, 40960 * 4);
    cudaFuncSetAttribute(decoder_kernel, cudaFuncAttributeMaxDynamicSharedMemorySize, 128 * 132 * 4);

    gates_kernel<<<NB * SL / 8, 256>>>(seq, emb, pos, Wr1, br1, Wr2, br2);
    conn_kernel<<<1, 64, NB * SL * MM * 4>>>(conn0);
    scan_kernel<<<NB * MM, 512, SCAN_SMEM_BYTES>>>(mem0, Wmsg, ln_g, ln_b,
                                                   eW1, eb1, e1g, e1b,
                                                   eW2, eb2, e2g, e2b, eW3, eb3);
    qkv_kernel<<<dim3(NB * SL / 16, 3), 256>>>(Wq, Wk, Wv);
    attn_kernel<<<dim3(NB * 4, SL / 8), 256, 40960 * 4>>>();
    gemm_out_kernel<<<NB * SL / 16, 256>>>(Wo, Wd1, bd1);
    decoder_kernel<<<dim3(NB * SL / 128, VOCAB / 64), 256, 128 * 132 * 4>>>(Wd2, bd2, (float*)d_out);
}